// round 10
// baseline (speedup 1.0000x reference)
#include <cuda_runtime.h>
#include <math.h>
#include <stdint.h>

#define NN   512        // nodes
#define KD   8          // edges per node
#define NNZ  4096       // incidences
#define FT   1386       // text features
#define FTP  1408       // padded to 32-multiple
#define HD   4096       // hidden
#define NH   8          // heads
#define NC   64         // code
#define EE   512        // hyperedges
#define HC   (NH*NC)    // 512
#define GC   (HC+NC)    // 576
#define WAC  (NH*HD)    // 32768
#define BR   80         // B rows for MV gemm: 64 W2T + att1 + att2 + 14 pad
#define DINV 0.125f     // node degree is exactly KD=8 by construction

// ---------------- scratch (static device memory) ----------------
__device__ float g_xpad[NN*FTP];      // tf32-rounded x, padded
__device__ float g_W1T[HD*FTP];       // tf32-rounded W1^T
__device__ float g_W2T[NC*HD];        // tf32-rounded W2^T
__device__ float g_Ball[NH*BR*HD];    // per-head B for MV gemm (rounded)
__device__ float g_BcatT[GC*HD];      // rows 0..511 = M^T; 512..575 = W2T
__device__ float g_xl[NN*HD];
__device__ float g_ef[EE*HD];
__device__ float g_he[EE*HD];
__device__ float g_featc[NN*HD];      // tf32-rounded feat (A of G gemm)
__device__ float g_V1[HD*NH];
__device__ float g_V2[HD*NH];
__device__ float g_sx[NN*NH];
__device__ float g_se[EE*NH];
__device__ float g_alpha[NNZ*NH];
__device__ float g_G[NN*GC];
__device__ float g_R[EE*HC];
__device__ float g_Y[NN*NC];
__device__ float g_ef2[EE*NC];
__device__ float g_bw2[NC];
__device__ int   g_bcnt[EE];
__device__ int   g_boff[EE];
__device__ int   g_csr[NNZ];
__device__ float g_Binv[EE];

// ---------------- helpers ----------------
__device__ __forceinline__ float tf32r(float x) {
    float y;
    asm("cvt.rna.tf32.f32 %0, %1;" : "=f"(y) : "f"(x));
    return y;
}
__device__ __forceinline__ uint32_t smem_u32(const void* p) {
    uint32_t a;
    asm("{ .reg .u64 t; cvta.to.shared.u64 t, %1; cvt.u32.u64 %0, t; }" : "=r"(a) : "l"(p));
    return a;
}
#define CP_ASYNC16(dst, src) \
    asm volatile("cp.async.cg.shared.global [%0], [%1], 16;" :: "r"(dst), "l"(src))
#define CP_COMMIT() asm volatile("cp.async.commit_group;" ::: "memory")
#define CP_WAIT1()  asm volatile("cp.async.wait_group 1;" ::: "memory")
#define CP_WAIT0()  asm volatile("cp.async.wait_group 0;" ::: "memory")

#define MMA_TF32(C, A0, A1, A2, A3, B0, B1) \
    asm volatile("mma.sync.aligned.m16n8k8.row.col.f32.tf32.tf32.f32 " \
        "{%0,%1,%2,%3},{%4,%5,%6,%7},{%8,%9},{%0,%1,%2,%3};" \
        : "+f"((C)[0]), "+f"((C)[1]), "+f"((C)[2]), "+f"((C)[3]) \
        : "r"(A0), "r"(A1), "r"(A2), "r"(A3), "r"(B0), "r"(B1))

__device__ __forceinline__ void ldsm4(uint32_t* r, uint32_t a) {
    asm volatile("ldmatrix.sync.aligned.m8n8.x4.shared.b16 {%0,%1,%2,%3}, [%4];"
        : "=r"(r[0]), "=r"(r[1]), "=r"(r[2]), "=r"(r[3]) : "r"(a));
}
__device__ __forceinline__ void ldsm2(uint32_t* r, uint32_t a) {
    asm volatile("ldmatrix.sync.aligned.m8n8.x2.shared.b16 {%0,%1}, [%2];"
        : "=r"(r[0]), "=r"(r[1]) : "r"(a));
}

// ============ tf32 mma.sync mainloop (dynamic smem; ldmatrix; cp.async A) ============
// C[128 x BN] += A[128 x 32*NCH] * B[BN x 32*NCH]^T
// smem layout: As = sm[0 .. 2*128*36), Bs = sm[2*128*36 .. +BN*36)
template<int BN, int NCH>
__device__ __forceinline__ void mma_mainloop(float* __restrict__ sm,
                                             const float* __restrict__ A, size_t lda,
                                             const float* __restrict__ B, size_t ldb,
                                             float (&acc)[2][BN/16][4]) {
    constexpr int NT = BN / 16;
    constexpr int PBN = (BN * 16) / 256;      // float2 B loads per thread
    float* Bs_ = sm + 2 * 128 * 36;
    const int tid = threadIdx.x, lane = tid & 31, wid = tid >> 5;
    const int wm = wid >> 1, wn = wid & 1;
    const int ar = tid >> 3, ac = (tid & 7) * 4;
    const int sub = lane >> 3, l7 = lane & 7;
    const uint32_t aBase = smem_u32(sm);
    const uint32_t bBase = smem_u32(Bs_);
    float2 pb[PBN];

    // precomputed ldmatrix lane addresses
    uint32_t aAddr[2];
#pragma unroll
    for (int mt = 0; mt < 2; mt++)
        aAddr[mt] = aBase + (uint32_t)(((wm * 32 + mt * 16 + l7 + (sub & 1) * 8) * 36) * 4)
                  + (uint32_t)((sub >> 1) * 16);
    uint32_t bAddr[(NT + 1) / 2];
#pragma unroll
    for (int p = 0; p < NT / 2; p++)
        bAddr[p] = bBase + (uint32_t)(((wn * (BN / 2) + p * 16 + l7 + (sub >> 1) * 8) * 36) * 4)
                 + (uint32_t)((sub & 1) * 16);
    if (NT & 1)
        bAddr[NT / 2] = bBase + (uint32_t)(((wn * (BN / 2) + (NT - 1) * 8 + l7) * 36) * 4)
                      + (uint32_t)((sub & 1) * 16);

    // prologue
#pragma unroll
    for (int p = 0; p < 4; p++) {
        uint32_t dst = aBase + (uint32_t)(((ar + p * 32) * 36 + ac) * 4);
        CP_ASYNC16(dst, A + (size_t)(ar + p * 32) * lda + ac);
    }
    CP_COMMIT();
#pragma unroll
    for (int p = 0; p < PBN; p++) {
        int idx = tid + p * 256;
        pb[p] = *(const float2*)&B[(size_t)(idx >> 4) * ldb + (idx & 15) * 2];
    }

    for (int c = 0; c < NCH; c++) {
        __syncthreads();
        if (c + 1 < NCH) {
            uint32_t sB = aBase + ((c + 1) & 1) * (128 * 36 * 4);
            int d0 = (c + 1) * 32;
#pragma unroll
            for (int p = 0; p < 4; p++) {
                uint32_t dst = sB + (uint32_t)(((ar + p * 32) * 36 + ac) * 4);
                CP_ASYNC16(dst, A + (size_t)(ar + p * 32) * lda + d0 + ac);
            }
            CP_COMMIT();
        }
#pragma unroll
        for (int p = 0; p < PBN; p++) {
            int idx = tid + p * 256;
            *(float2*)&Bs_[(idx >> 4) * 36 + (idx & 15) * 2] = pb[p];
        }
        if (c + 1 < NCH) CP_WAIT1(); else CP_WAIT0();
        __syncthreads();
        if (c + 1 < NCH) {
            int d0 = (c + 1) * 32;
#pragma unroll
            for (int p = 0; p < PBN; p++) {
                int idx = tid + p * 256;
                pb[p] = *(const float2*)&B[(size_t)(idx >> 4) * ldb + d0 + (idx & 15) * 2];
            }
        }
        const uint32_t aS = (uint32_t)(c & 1) * (128 * 36 * 4);
#pragma unroll
        for (int kk = 0; kk < 4; kk++) {
            uint32_t af[2][4];
            ldsm4(af[0], aAddr[0] + aS + kk * 32);
            ldsm4(af[1], aAddr[1] + aS + kk * 32);
            uint32_t bf[NT][2];
#pragma unroll
            for (int p = 0; p < NT / 2; p++) {
                uint32_t t[4];
                ldsm4(t, bAddr[p] + kk * 32);
                bf[2 * p][0] = t[0]; bf[2 * p][1] = t[1];
                bf[2 * p + 1][0] = t[2]; bf[2 * p + 1][1] = t[3];
            }
            if (NT & 1) ldsm2(bf[NT - 1], bAddr[NT / 2] + kk * 32);
#pragma unroll
            for (int nt = 0; nt < NT; nt++)
#pragma unroll
                for (int mt = 0; mt < 2; mt++)
                    MMA_TF32(acc[mt][nt], af[mt][0], af[mt][1], af[mt][2], af[mt][3],
                             bf[nt][0], bf[nt][1]);
        }
    }
}

#define SMEM_FUSED (2*128*36*4 + 80*36*4)   // 48384 B (< 48 KB default dyn limit)
#define SMEM_G     (2*128*36*4 + 32*36*4)   // 41472 B

// ---------------- fused GEMM: CTAs 0..255 = tgMV (long pole), 256..511 = tg1 ----------------
__global__ void __launch_bounds__(256, 3) k_tgfused(const float* __restrict__ Wa) {
    extern __shared__ float dsm[];
    int b = blockIdx.x;
    int lane = threadIdx.x & 31, wid = threadIdx.x >> 5;
    if (b < 256) {                                         // ---- tgMV ----
        float acc[2][5][4] = {};
        int kxb = b & 31, h = b >> 5;
        const float* A = Wa + (size_t)h * HD + (size_t)kxb * 128 * WAC;
        const float* B = g_Ball + (size_t)h * BR * HD;
        mma_mainloop<80, HD / 32>(dsm, A, WAC, B, HD, acc);   // Wa tf32-truncated
        int k0 = kxb * 128 + (wid >> 1) * 32 + (lane >> 2);
        int nb = (wid & 1) * 40 + 2 * (lane & 3);
#pragma unroll
        for (int mt = 0; mt < 2; mt++) {
            int k = k0 + mt * 16;
#pragma unroll
            for (int nt = 0; nt < 5; nt++) {
                int n = nb + nt * 8;
                if (n < 64) {
                    g_BcatT[(size_t)(h * 64 + n) * HD + k]         = tf32r(acc[mt][nt][0]);
                    g_BcatT[(size_t)(h * 64 + n + 1) * HD + k]     = tf32r(acc[mt][nt][1]);
                    g_BcatT[(size_t)(h * 64 + n) * HD + k + 8]     = tf32r(acc[mt][nt][2]);
                    g_BcatT[(size_t)(h * 64 + n + 1) * HD + k + 8] = tf32r(acc[mt][nt][3]);
                } else if (n == 64) {
                    g_V1[k * NH + h]       = acc[mt][nt][0];
                    g_V2[k * NH + h]       = acc[mt][nt][1];
                    g_V1[(k + 8) * NH + h] = acc[mt][nt][2];
                    g_V2[(k + 8) * NH + h] = acc[mt][nt][3];
                }
            }
        }
    } else {                                               // ---- tg1 ----
        b -= 256;
        float acc[2][4][4] = {};
        int gx = b >> 6, gy = b & 63;
        const float* A = g_xpad + (size_t)gx * 128 * FTP;
        const float* B = g_W1T + (size_t)gy * 64 * FTP;
        mma_mainloop<64, FTP / 32>(dsm, A, FTP, B, FTP, acc);
        int rb = gx * 128 + (wid >> 1) * 32 + (lane >> 2);
        int cb = gy * 64 + (wid & 1) * 32 + 2 * (lane & 3);
#pragma unroll
        for (int mt = 0; mt < 2; mt++)
#pragma unroll
            for (int nt = 0; nt < 4; nt++) {
                int r = rb + mt * 16, cc = cb + nt * 8;
                *(float2*)&g_xl[(size_t)r * HD + cc] = make_float2(acc[mt][nt][0], acc[mt][nt][1]);
                *(float2*)&g_xl[(size_t)(r + 8) * HD + cc] = make_float2(acc[mt][nt][2], acc[mt][nt][3]);
            }
    }
}

__global__ void __launch_bounds__(256, 3) k_tgG() {       // G += featc @ BcatT^T (split-K 2)
    extern __shared__ float dsm[];
    float acc[2][2][4] = {};
    int m0 = blockIdx.x * 128, n0 = blockIdx.y * 32, kz = blockIdx.z * 2048;
    const float* A = g_featc + (size_t)m0 * HD + kz;
    const float* B = g_BcatT + (size_t)n0 * HD + kz;
    mma_mainloop<32, 64>(dsm, A, HD, B, HD, acc);
    int lane = threadIdx.x & 31, wid = threadIdx.x >> 5;
    int rb = m0 + (wid >> 1) * 32 + (lane >> 2);
    int cb = n0 + (wid & 1) * 16 + 2 * (lane & 3);
#pragma unroll
    for (int mt = 0; mt < 2; mt++)
#pragma unroll
        for (int nt = 0; nt < 2; nt++) {
            int r = rb + mt * 16, cc = cb + nt * 8;
            atomicAdd(&g_G[(size_t)r * GC + cc],           acc[mt][nt][0]);
            atomicAdd(&g_G[(size_t)r * GC + cc + 1],       acc[mt][nt][1]);
            atomicAdd(&g_G[(size_t)(r + 8) * GC + cc],     acc[mt][nt][2]);
            atomicAdd(&g_G[(size_t)(r + 8) * GC + cc + 1], acc[mt][nt][3]);
        }
}

// ---------------- fused prep: xpad | W1T | W2T(+BcatT tail) | zero-G | bw2 ----------------
#define NB_XPAD (NN*FTP/256)          // 2816
#define NB_W1T  ((FTP/32)*(HD/32))    // 5632
#define NB_W2T  ((HD/32)*(NC/32))     // 256
#define NB_GZ   (NN*GC/256)           // 1152
__global__ void __launch_bounds__(256) k_prepA(const float* __restrict__ x,
                                               const float* __restrict__ W1,
                                               const float* __restrict__ W2,
                                               const float* __restrict__ ba) {
    __shared__ float t[32][33];
    __shared__ float red[256];
    int b = blockIdx.x, tid = threadIdx.x;
    if (b < NB_XPAD) {                                   // ---- xpad ----
        int i = b * 256 + tid;
        int r = i / FTP, c = i % FTP;
        g_xpad[i] = (c < FT) ? tf32r(x[r * FT + c]) : 0.0f;
        return;
    }
    b -= NB_XPAD;
    if (b < NB_W1T) {                                    // ---- W1T transpose ----
        int ky = b / (HD / 32), nx = b % (HD / 32);
        int kb = ky * 32, nb = nx * 32;
        int tx = tid & 31, ty = tid >> 5;
        for (int i = ty; i < 32; i += 8) {
            int k = kb + i;
            t[i][tx] = (k < FT) ? tf32r(W1[(size_t)k * HD + nb + tx]) : 0.0f;
        }
        __syncthreads();
        for (int i = ty; i < 32; i += 8)
            g_W1T[(size_t)(nb + i) * FTP + kb + tx] = t[tx][i];
        return;
    }
    b -= NB_W1T;
    if (b < NB_W2T) {                                    // ---- W2T + BcatT tail ----
        int kb = (b >> 1) * 32, nb = (b & 1) * 32;
        int tx = tid & 31, ty = tid >> 5;
        for (int i = ty; i < 32; i += 8)
            t[i][tx] = tf32r(W2[(size_t)(kb + i) * NC + nb + tx]);
        __syncthreads();
        for (int i = ty; i < 32; i += 8) {
            float v = t[tx][i];
            g_W2T[(size_t)(nb + i) * HD + kb + tx] = v;
            g_BcatT[(size_t)(HC + nb + i) * HD + kb + tx] = v;
        }
        return;
    }
    b -= NB_W2T;
    if (b < NB_GZ) {                                     // ---- zero G (split-K atomics) ----
        g_G[b * 256 + tid] = 0.0f;
        return;
    }
    // ---- bw2 = ba @ W2 (1 block) ----
    int c = tid & 63, sl = tid >> 6;
    float acc = 0.0f;
    for (int d = sl * 1024; d < (sl + 1) * 1024; d++) acc += ba[d] * W2[d * NC + c];
    red[tid] = acc;
    __syncthreads();
    if (sl == 0) g_bw2[c] = red[c] + red[c + 64] + red[c + 128] + red[c + 192];
}

__global__ void k_fillB(const float* __restrict__ att) {
    size_t i = (size_t)blockIdx.x * 256 + threadIdx.x;    // NH*BR*HD
    if (i >= (size_t)NH * BR * HD) return;
    int d = (int)(i & (HD - 1));
    int rh = (int)(i >> 12);
    int r = rh % BR, h = rh / BR;
    float v;
    if (r < 64)       v = g_W2T[(size_t)r * HD + d];
    else if (r == 64) v = tf32r(att[h * 2 * HD + d]);
    else if (r == 65) v = tf32r(att[h * 2 * HD + HD + d]);
    else              v = 0.0f;
    g_Ball[i] = v;
}

// ---------------- fused CSR: per-warp count + offset + place (deterministic) ----------------
__global__ void __launch_bounds__(256) k_csr(const int* __restrict__ edge) {
    __shared__ int se_[NNZ];
    int tid = threadIdx.x;
    for (int i = tid; i < NNZ; i += 256) se_[i] = edge[i];
    __syncthreads();
    int lane = tid & 31;
    int e = blockIdx.x * 8 + (tid >> 5);
    int nlt = 0, cnt = 0;
    for (int i = lane; i < NNZ; i += 32) {
        int v = se_[i];
        nlt += __popc(__ballot_sync(0xFFFFFFFFu, v < e));
        cnt += __popc(__ballot_sync(0xFFFFFFFFu, v == e));
    }
    int w = nlt;
    for (int i = lane; i < NNZ; i += 32) {
        int v = se_[i];
        unsigned m = __ballot_sync(0xFFFFFFFFu, v == e);
        if (v == e)
            g_csr[w + __popc(m & ((1u << lane) - 1u))] = i;
        w += __popc(m);
    }
    if (lane == 0) {
        g_bcnt[e] = cnt;
        g_boff[e] = nlt;
        g_Binv[e] = (cnt > 0) ? 1.0f / (float)cnt : 0.0f;
    }
}

// ---------------- hgc1 gathers (float4) ----------------
__global__ void __launch_bounds__(256) k_edgefeat() {
    int e = blockIdx.x;
    int d4 = blockIdx.y * 256 + threadIdx.x;
    int off = g_boff[e], cnt = g_bcnt[e];
    float4 acc = make_float4(0.f, 0.f, 0.f, 0.f);
    const float4* xl4 = (const float4*)g_xl;
    for (int t = 0; t < cnt; t++) {
        int i = g_csr[off + t];
        float4 v = xl4[(size_t)(i >> 3) * (HD / 4) + d4];
        acc.x += v.x; acc.y += v.y; acc.z += v.z; acc.w += v.w;
    }
    float bi = g_Binv[e];
    acc.x *= bi; acc.y *= bi; acc.z *= bi; acc.w *= bi;
    ((float4*)g_ef)[(size_t)e * (HD / 4) + d4] = acc;
}
__global__ void __launch_bounds__(256) k_feat(const int* __restrict__ edge,
                                              const float* __restrict__ b1,
                                              float* __restrict__ feat) {
    int n = blockIdx.x;
    int d4 = blockIdx.y * 256 + threadIdx.x;
    float4 acc = make_float4(0.f, 0.f, 0.f, 0.f);
    const float4* ef4 = (const float4*)g_ef;
#pragma unroll
    for (int j = 0; j < KD; j++) {
        int e = edge[n * KD + j];
        float4 v = ef4[(size_t)e * (HD / 4) + d4];
        acc.x += v.x; acc.y += v.y; acc.z += v.z; acc.w += v.w;
    }
    float4 bb = ((const float4*)b1)[d4];
    float4 r, rc;
    r.x = fmaxf(acc.x * DINV + bb.x, 0.f);
    r.y = fmaxf(acc.y * DINV + bb.y, 0.f);
    r.z = fmaxf(acc.z * DINV + bb.z, 0.f);
    r.w = fmaxf(acc.w * DINV + bb.w, 0.f);
    rc.x = tf32r(r.x); rc.y = tf32r(r.y); rc.z = tf32r(r.z); rc.w = tf32r(r.w);
    ((float4*)feat)[(size_t)n * (HD / 4) + d4] = r;       // exact output #1
    ((float4*)g_featc)[(size_t)n * (HD / 4) + d4] = rc;   // rounded A for G gemm
}
__global__ void __launch_bounds__(256) k_he(const float* __restrict__ feat) {
    int e = blockIdx.x;
    int d4 = blockIdx.y * 256 + threadIdx.x;
    int off = g_boff[e], cnt = g_bcnt[e];
    float4 acc = make_float4(0.f, 0.f, 0.f, 0.f);
    const float4* f4 = (const float4*)feat;
    for (int t = 0; t < cnt; t++) {
        int i = g_csr[off + t];
        float4 v = f4[(size_t)(i >> 3) * (HD / 4) + d4];
        acc.x += v.x; acc.y += v.y; acc.z += v.z; acc.w += v.w;
    }
    float inv = 1.0f / (float)cnt;
    acc.x *= inv; acc.y *= inv; acc.z *= inv; acc.w *= inv;
    ((float4*)g_he)[(size_t)e * (HD / 4) + d4] = acc;
}

// ---------------- attention logits + softmax ----------------
__global__ void __launch_bounds__(256) k_sxse(const float* __restrict__ feat) {
    int b = blockIdx.x;
    const float* row; const float* V; float* out;
    if (b < NN) { row = feat + (size_t)b * HD; V = g_V1; out = g_sx + b * NH; }
    else { int e = b - NN; row = g_he + (size_t)e * HD; V = g_V2; out = g_se + e * NH; }
    float acc[NH] = {};
    for (int k = threadIdx.x; k < HD; k += 256) {
        float xv = row[k];
        float4 w0 = *(const float4*)&V[k * NH];
        float4 w1 = *(const float4*)&V[k * NH + 4];
        acc[0] += xv * w0.x; acc[1] += xv * w0.y; acc[2] += xv * w0.z; acc[3] += xv * w0.w;
        acc[4] += xv * w1.x; acc[5] += xv * w1.y; acc[6] += xv * w1.z; acc[7] += xv * w1.w;
    }
    __shared__ float red[NH][256];
#pragma unroll
    for (int h = 0; h < NH; h++) red[h][threadIdx.x] = acc[h];
    __syncthreads();
    for (int s = 128; s > 0; s >>= 1) {
        if (threadIdx.x < s) {
#pragma unroll
            for (int h = 0; h < NH; h++) red[h][threadIdx.x] += red[h][threadIdx.x + s];
        }
        __syncthreads();
    }
    if (threadIdx.x < NH) out[threadIdx.x] = red[threadIdx.x][0];
}
__global__ void k_alpha(const int* __restrict__ edge) {
    int id = blockIdx.x * blockDim.x + threadIdx.x;
    if (id >= NN * NH) return;
    int n = id >> 3, h = id & 7;
    float sxv = g_sx[n * NH + h];
    float l[KD];
    float m = -1e30f;
#pragma unroll
    for (int j = 0; j < KD; j++) {
        int e = edge[n * KD + j];
        float t = sxv + g_se[e * NH + h];
        t = t > 0.0f ? t : 0.2f * t;
        l[j] = t;
        m = fmaxf(m, t);
    }
    float s = 0.0f;
#pragma unroll
    for (int j = 0; j < KD; j++) { l[j] = expf(l[j] - m); s += l[j]; }
    float inv = 1.0f / s;
#pragma unroll
    for (int j = 0; j < KD; j++) g_alpha[(n * KD + j) * NH + h] = l[j] * inv;
}

// ---------------- CODE-space aggregation ----------------
__global__ void __launch_bounds__(256) k_R() {
    int e = blockIdx.x;
    int hc = blockIdx.y * 256 + threadIdx.x;
    int h = hc >> 6;
    int off = g_boff[e], cnt = g_bcnt[e];
    float acc = 0.0f;
    for (int t = 0; t < cnt; t++) {
        int i = g_csr[off + t];
        acc += g_alpha[i * NH + h] * g_G[(i >> 3) * GC + hc];
    }
    g_R[e * HC + hc] = acc * g_Binv[e];
}
__global__ void k_Y(const int* __restrict__ edge) {
    int n = blockIdx.x, c = threadIdx.x;
    float acc = g_G[n * GC + HC + c] + g_bw2[c];
    float s = 0.0f;
#pragma unroll
    for (int j = 0; j < KD; j++) {
        int e = edge[n * KD + j];
        const float* al = &g_alpha[(n * KD + j) * NH];
        const float* Rr = &g_R[e * HC + c];
#pragma unroll
        for (int h = 0; h < NH; h++) s += al[h] * Rr[h * NC];
    }
    g_Y[n * NC + c] = acc + s * DINV * (1.0f / NH);
}
__global__ void k_ef2() {
    int e = blockIdx.x, c = threadIdx.x;
    int off = g_boff[e], cnt = g_bcnt[e];
    float acc = 0.0f;
    for (int t = 0; t < cnt; t++) {
        int i = g_csr[off + t];
        acc += g_Y[(i >> 3) * NC + c];
    }
    g_ef2[e * NC + c] = acc * g_Binv[e];
}
__global__ void k_out(const int* __restrict__ edge, const float* __restrict__ b2,
                      float* __restrict__ out) {
    int n = blockIdx.x, c = threadIdx.x;
    float acc = 0.0f;
#pragma unroll
    for (int j = 0; j < KD; j++) {
        int e = edge[n * KD + j];
        acc += g_ef2[e * NC + c];
    }
    float hid = acc * DINV + b2[c];
    out[(size_t)NN * HD + n * NC + c] = hid;
    out[(size_t)NN * HD + NN * NC + n * NC + c] = tanhf(hid);
}

// ---------------- launch ----------------
extern "C" void kernel_launch(void* const* d_in, const int* in_sizes, int n_in,
                              void* d_out, int out_size) {
    const float* x    = (const float*)d_in[0];
    const int*   edge = (const int*)  d_in[2];
    const float* W1   = (const float*)d_in[3];
    const float* b1   = (const float*)d_in[4];
    const float* Wa   = (const float*)d_in[5];
    const float* att  = (const float*)d_in[6];
    const float* ba   = (const float*)d_in[7];
    const float* W2   = (const float*)d_in[8];
    const float* b2   = (const float*)d_in[9];
    float* out  = (float*)d_out;
    float* feat = out;

    k_csr<<<64, 256>>>(edge);                                         // 1
    k_prepA<<<NB_XPAD + NB_W1T + NB_W2T + NB_GZ + 1, 256>>>(x, W1, W2, ba); // 2
    k_fillB<<<(NH * BR * HD + 255) / 256, 256>>>(att);                // 3
    k_tgfused<<<512, 256, SMEM_FUSED>>>(Wa);                          // 4  tgMV || tg1
    k_edgefeat<<<dim3(EE, 4), 256>>>();                               // 5
    k_feat<<<dim3(NN, 4), 256>>>(edge, b1, feat);                     // 6
    k_he<<<dim3(EE, 4), 256>>>(feat);                                 // 7
    k_sxse<<<NN + EE, 256>>>(feat);                                   // 8
    k_alpha<<<16, 256>>>(edge);                                       // 9
    k_tgG<<<dim3(4, 18, 2), 256, SMEM_G>>>();                         // 10
    k_R<<<dim3(EE, 2), 256>>>();                                      // 11
    k_Y<<<NN, 64>>>(edge);                                            // 12
    k_ef2<<<EE, 64>>>();                                              // 13
    k_out<<<NN, 64>>>(edge, b2, out);                                 // 14
}

// round 11
// speedup vs baseline: 1.0332x; 1.0332x over previous
#include <cuda_runtime.h>
#include <math.h>
#include <stdint.h>

#define NN   512        // nodes
#define KD   8          // edges per node
#define NNZ  4096       // incidences
#define FT   1386       // text features
#define FTP  1408       // padded to 32-multiple
#define HD   4096       // hidden
#define NH   8          // heads
#define NC   64         // code
#define EE   512        // hyperedges
#define HC   (NH*NC)    // 512
#define GC   (HC+NC)    // 576
#define WAC  (NH*HD)    // 32768
#define BR   80         // B rows for MV gemm: 64 W2T + att1 + att2 + 14 pad
#define DINV 0.125f     // node degree is exactly KD=8 by construction

// ---------------- scratch (static device memory) ----------------
__device__ float g_xpad[NN*FTP];      // tf32-rounded x, padded
__device__ float g_W1T[HD*FTP];       // tf32-rounded W1^T
__device__ float g_W2T[NC*HD];        // tf32-rounded W2^T
__device__ float g_Ball[NH*BR*HD];    // per-head B for MV gemm (rounded)
__device__ float g_BcatT[GC*HD];      // rows 0..511 = M^T; 512..575 = W2T
__device__ float g_xl[NN*HD];
__device__ float g_ef[EE*HD];
__device__ float g_he[EE*HD];
__device__ float g_featc[NN*HD];      // tf32-rounded feat (A of G gemm)
__device__ float g_V1[HD*NH];
__device__ float g_V2[HD*NH];
__device__ float g_sx[NN*NH];
__device__ float g_se[EE*NH];
__device__ float g_alpha[NNZ*NH];
__device__ float g_G[NN*GC];
__device__ float g_R[EE*HC];
__device__ float g_Y[NN*NC];
__device__ float g_ef2[EE*NC];
__device__ float g_bw2[NC];
__device__ int   g_bcnt[EE];
__device__ int   g_boff[EE];
__device__ int   g_csr[NNZ];
__device__ float g_Binv[EE];

// ---------------- helpers ----------------
__device__ __forceinline__ float tf32r(float x) {
    float y;
    asm("cvt.rna.tf32.f32 %0, %1;" : "=f"(y) : "f"(x));
    return y;
}
__device__ __forceinline__ uint32_t smem_u32(const void* p) {
    uint32_t a;
    asm("{ .reg .u64 t; cvta.to.shared.u64 t, %1; cvt.u32.u64 %0, t; }" : "=r"(a) : "l"(p));
    return a;
}
#define CP_ASYNC16(dst, src) \
    asm volatile("cp.async.cg.shared.global [%0], [%1], 16;" :: "r"(dst), "l"(src))
#define CP_COMMIT() asm volatile("cp.async.commit_group;" ::: "memory")
#define CP_WAIT2()  asm volatile("cp.async.wait_group 2;" ::: "memory")
#define CP_WAIT1()  asm volatile("cp.async.wait_group 1;" ::: "memory")
#define CP_WAIT0()  asm volatile("cp.async.wait_group 0;" ::: "memory")

#define MMA_TF32(C, A0, A1, A2, A3, B0, B1) \
    asm volatile("mma.sync.aligned.m16n8k8.row.col.f32.tf32.tf32.f32 " \
        "{%0,%1,%2,%3},{%4,%5,%6,%7},{%8,%9},{%0,%1,%2,%3};" \
        : "+f"((C)[0]), "+f"((C)[1]), "+f"((C)[2]), "+f"((C)[3]) \
        : "r"(A0), "r"(A1), "r"(A2), "r"(A3), "r"(B0), "r"(B1))

__device__ __forceinline__ void ldsm4(uint32_t* r, uint32_t a) {
    asm volatile("ldmatrix.sync.aligned.m8n8.x4.shared.b16 {%0,%1,%2,%3}, [%4];"
        : "=r"(r[0]), "=r"(r[1]), "=r"(r[2]), "=r"(r[3]) : "r"(a));
}
__device__ __forceinline__ void ldsm2(uint32_t* r, uint32_t a) {
    asm volatile("ldmatrix.sync.aligned.m8n8.x2.shared.b16 {%0,%1}, [%2];"
        : "=r"(r[0]), "=r"(r[1]) : "r"(a));
}

#define ASTAGE_F (128*36)              // floats per A stage
#define ASTAGE_B (ASTAGE_F*4)          // bytes per A stage

// ============ tf32 mma.sync mainloop v3: 4-stage A cp.async, 2-stage Bs, 1 sync/chunk ====
// C[128 x BN] += A[128 x 32*NCH] * B[BN x 32*NCH]^T    (NCH >= 4)
// smem: As = sm[0 .. 4*ASTAGE_F), Bs = sm[4*ASTAGE_F .. + 2*BN*36)
template<int BN, int NCH>
__device__ __forceinline__ void mma_v3(float* __restrict__ sm,
                                       const float* __restrict__ A, size_t lda,
                                       const float* __restrict__ B, size_t ldb,
                                       float (&acc)[2][BN/16][4]) {
    constexpr int NT = BN / 16;
    constexpr int PBN = (BN * 16) / 256;       // float2 B loads per thread
    constexpr int BSTAGE_F = BN * 36;
    float* Bs_ = sm + 4 * ASTAGE_F;
    const int tid = threadIdx.x, lane = tid & 31, wid = tid >> 5;
    const int wm = wid >> 1, wn = wid & 1;
    const int ar = tid >> 3, ac = (tid & 7) * 4;
    const int sub = lane >> 3, l7 = lane & 7;
    const uint32_t aBase = smem_u32(sm);
    const uint32_t bBase = smem_u32(Bs_);
    float2 pb[PBN];

    // ldmatrix lane addresses (stage 0)
    uint32_t aAddr[2];
#pragma unroll
    for (int mt = 0; mt < 2; mt++)
        aAddr[mt] = aBase + (uint32_t)(((wm * 32 + mt * 16 + l7 + (sub & 1) * 8) * 36) * 4)
                  + (uint32_t)((sub >> 1) * 16);
    uint32_t bAddr[(NT + 1) / 2];
#pragma unroll
    for (int p = 0; p < NT / 2; p++)
        bAddr[p] = bBase + (uint32_t)(((wn * (BN / 2) + p * 16 + l7 + (sub >> 1) * 8) * 36) * 4)
                 + (uint32_t)((sub & 1) * 16);
    if (NT & 1)
        bAddr[NT / 2] = bBase + (uint32_t)(((wn * (BN / 2) + (NT - 1) * 8 + l7) * 36) * 4)
                      + (uint32_t)((sub & 1) * 16);

    // prologue: A chunks 0..2 into stages 0..2; B chunk 0 into regs
#pragma unroll
    for (int s = 0; s < 3; s++) {
        int d0 = s * 32;
        uint32_t sB = aBase + (uint32_t)s * ASTAGE_B;
#pragma unroll
        for (int p = 0; p < 4; p++) {
            uint32_t dst = sB + (uint32_t)(((ar + p * 32) * 36 + ac) * 4);
            CP_ASYNC16(dst, A + (size_t)(ar + p * 32) * lda + d0 + ac);
        }
        CP_COMMIT();
    }
#pragma unroll
    for (int p = 0; p < PBN; p++) {
        int idx = tid + p * 256;
        pb[p] = *(const float2*)&B[(size_t)(idx >> 4) * ldb + (idx & 15) * 2];
    }

    for (int c = 0; c < NCH; c++) {
        // wait for A chunk c (younger pending groups stay in flight)
        if (c + 2 < NCH)      CP_WAIT2();
        else if (c + 1 < NCH) CP_WAIT1();
        else                  CP_WAIT0();
        // store B chunk c (buffer c&1; last readers finished before previous sync)
#pragma unroll
        for (int p = 0; p < PBN; p++) {
            int idx = tid + p * 256;
            *(float2*)&Bs_[(c & 1) * BSTAGE_F + (idx >> 4) * 36 + (idx & 15) * 2] = pb[p];
        }
        __syncthreads();
        // prefetch B chunk c+1 (global->regs, overlaps compute)
        if (c + 1 < NCH) {
            int d0 = (c + 1) * 32;
#pragma unroll
            for (int p = 0; p < PBN; p++) {
                int idx = tid + p * 256;
                pb[p] = *(const float2*)&B[(size_t)(idx >> 4) * ldb + d0 + (idx & 15) * 2];
            }
        }
        // issue A chunk c+3 into stage (c+3)&3 (freed by compute(c-1), done pre-sync)
        if (c + 3 < NCH) {
            int d0 = (c + 3) * 32;
            uint32_t sB = aBase + (uint32_t)((c + 3) & 3) * ASTAGE_B;
#pragma unroll
            for (int p = 0; p < 4; p++) {
                uint32_t dst = sB + (uint32_t)(((ar + p * 32) * 36 + ac) * 4);
                CP_ASYNC16(dst, A + (size_t)(ar + p * 32) * lda + d0 + ac);
            }
            CP_COMMIT();
        }
        // compute chunk c
        const uint32_t aS = (uint32_t)(c & 3) * ASTAGE_B;
        const uint32_t bS = (uint32_t)(c & 1) * (BSTAGE_F * 4);
#pragma unroll
        for (int kk = 0; kk < 4; kk++) {
            uint32_t af[2][4];
            ldsm4(af[0], aAddr[0] + aS + kk * 32);
            ldsm4(af[1], aAddr[1] + aS + kk * 32);
            uint32_t bf[NT][2];
#pragma unroll
            for (int p = 0; p < NT / 2; p++) {
                uint32_t t[4];
                ldsm4(t, bAddr[p] + bS + kk * 32);
                bf[2 * p][0] = t[0]; bf[2 * p][1] = t[1];
                bf[2 * p + 1][0] = t[2]; bf[2 * p + 1][1] = t[3];
            }
            if (NT & 1) ldsm2(bf[NT - 1], bAddr[NT / 2] + bS + kk * 32);
#pragma unroll
            for (int nt = 0; nt < NT; nt++)
#pragma unroll
                for (int mt = 0; mt < 2; mt++)
                    MMA_TF32(acc[mt][nt], af[mt][0], af[mt][1], af[mt][2], af[mt][3],
                             bf[nt][0], bf[nt][1]);
        }
    }
}

#define SMEM_MV (4*ASTAGE_B + 2*80*36*4)   // 96768
#define SMEM_T1 (4*ASTAGE_B + 2*64*36*4)   // 92160
#define SMEM_GG (4*ASTAGE_B + 2*32*36*4)   // 82944

// ---------------- GEMM kernels ----------------
__global__ void __launch_bounds__(256) k_tgMV(const float* __restrict__ Wa) {
    extern __shared__ float dsm[];
    float acc[2][5][4] = {};
    int h = blockIdx.y;
    const float* A = Wa + (size_t)h * HD + (size_t)blockIdx.x * 128 * WAC;
    const float* B = g_Ball + (size_t)h * BR * HD;
    mma_v3<80, HD / 32>(dsm, A, WAC, B, HD, acc);   // Wa operands tf32-truncated
    int lane = threadIdx.x & 31, wid = threadIdx.x >> 5;
    int k0 = blockIdx.x * 128 + (wid >> 1) * 32 + (lane >> 2);
    int nb = (wid & 1) * 40 + 2 * (lane & 3);
#pragma unroll
    for (int mt = 0; mt < 2; mt++) {
        int k = k0 + mt * 16;
#pragma unroll
        for (int nt = 0; nt < 5; nt++) {
            int n = nb + nt * 8;
            if (n < 64) {
                g_BcatT[(size_t)(h * 64 + n) * HD + k]         = tf32r(acc[mt][nt][0]);
                g_BcatT[(size_t)(h * 64 + n + 1) * HD + k]     = tf32r(acc[mt][nt][1]);
                g_BcatT[(size_t)(h * 64 + n) * HD + k + 8]     = tf32r(acc[mt][nt][2]);
                g_BcatT[(size_t)(h * 64 + n + 1) * HD + k + 8] = tf32r(acc[mt][nt][3]);
            } else if (n == 64) {
                g_V1[k * NH + h]       = acc[mt][nt][0];
                g_V2[k * NH + h]       = acc[mt][nt][1];
                g_V1[(k + 8) * NH + h] = acc[mt][nt][2];
                g_V2[(k + 8) * NH + h] = acc[mt][nt][3];
            }
        }
    }
}

__global__ void __launch_bounds__(256) k_tg1() {       // xl = xpad @ W1T^T
    extern __shared__ float dsm[];
    float acc[2][4][4] = {};
    const float* A = g_xpad + (size_t)blockIdx.x * 128 * FTP;
    const float* B = g_W1T + (size_t)blockIdx.y * 64 * FTP;
    mma_v3<64, FTP / 32>(dsm, A, FTP, B, FTP, acc);
    int lane = threadIdx.x & 31, wid = threadIdx.x >> 5;
    int rb = blockIdx.x * 128 + (wid >> 1) * 32 + (lane >> 2);
    int cb = blockIdx.y * 64 + (wid & 1) * 32 + 2 * (lane & 3);
#pragma unroll
    for (int mt = 0; mt < 2; mt++)
#pragma unroll
        for (int nt = 0; nt < 4; nt++) {
            int r = rb + mt * 16, cc = cb + nt * 8;
            *(float2*)&g_xl[(size_t)r * HD + cc] = make_float2(acc[mt][nt][0], acc[mt][nt][1]);
            *(float2*)&g_xl[(size_t)(r + 8) * HD + cc] = make_float2(acc[mt][nt][2], acc[mt][nt][3]);
        }
}

__global__ void __launch_bounds__(256) k_tgG() {       // G += featc @ BcatT^T (split-K 2)
    extern __shared__ float dsm[];
    float acc[2][2][4] = {};
    int m0 = blockIdx.x * 128, n0 = blockIdx.y * 32, kz = blockIdx.z * 2048;
    const float* A = g_featc + (size_t)m0 * HD + kz;
    const float* B = g_BcatT + (size_t)n0 * HD + kz;
    mma_v3<32, 64>(dsm, A, HD, B, HD, acc);
    int lane = threadIdx.x & 31, wid = threadIdx.x >> 5;
    int rb = m0 + (wid >> 1) * 32 + (lane >> 2);
    int cb = n0 + (wid & 1) * 16 + 2 * (lane & 3);
#pragma unroll
    for (int mt = 0; mt < 2; mt++)
#pragma unroll
        for (int nt = 0; nt < 2; nt++) {
            int r = rb + mt * 16, cc = cb + nt * 8;
            atomicAdd(&g_G[(size_t)r * GC + cc],           acc[mt][nt][0]);
            atomicAdd(&g_G[(size_t)r * GC + cc + 1],       acc[mt][nt][1]);
            atomicAdd(&g_G[(size_t)(r + 8) * GC + cc],     acc[mt][nt][2]);
            atomicAdd(&g_G[(size_t)(r + 8) * GC + cc + 1], acc[mt][nt][3]);
        }
}

// ---------------- fused prep: xpad | W1T | W2T(+BcatT tail) | zero-G | bw2 ----------------
#define NB_XPAD (NN*FTP/256)          // 2816
#define NB_W1T  ((FTP/32)*(HD/32))    // 5632
#define NB_W2T  ((HD/32)*(NC/32))     // 256
#define NB_GZ   (NN*GC/256)           // 1152
__global__ void __launch_bounds__(256) k_prepA(const float* __restrict__ x,
                                               const float* __restrict__ W1,
                                               const float* __restrict__ W2,
                                               const float* __restrict__ ba) {
    __shared__ float t[32][33];
    __shared__ float red[256];
    int b = blockIdx.x, tid = threadIdx.x;
    if (b < NB_XPAD) {                                   // ---- xpad ----
        int i = b * 256 + tid;
        int r = i / FTP, c = i % FTP;
        g_xpad[i] = (c < FT) ? tf32r(x[r * FT + c]) : 0.0f;
        return;
    }
    b -= NB_XPAD;
    if (b < NB_W1T) {                                    // ---- W1T transpose ----
        int ky = b / (HD / 32), nx = b % (HD / 32);
        int kb = ky * 32, nb = nx * 32;
        int tx = tid & 31, ty = tid >> 5;
        for (int i = ty; i < 32; i += 8) {
            int k = kb + i;
            t[i][tx] = (k < FT) ? tf32r(W1[(size_t)k * HD + nb + tx]) : 0.0f;
        }
        __syncthreads();
        for (int i = ty; i < 32; i += 8)
            g_W1T[(size_t)(nb + i) * FTP + kb + tx] = t[tx][i];
        return;
    }
    b -= NB_W1T;
    if (b < NB_W2T) {                                    // ---- W2T + BcatT tail ----
        int kb = (b >> 1) * 32, nb = (b & 1) * 32;
        int tx = tid & 31, ty = tid >> 5;
        for (int i = ty; i < 32; i += 8)
            t[i][tx] = tf32r(W2[(size_t)(kb + i) * NC + nb + tx]);
        __syncthreads();
        for (int i = ty; i < 32; i += 8) {
            float v = t[tx][i];
            g_W2T[(size_t)(nb + i) * HD + kb + tx] = v;
            g_BcatT[(size_t)(HC + nb + i) * HD + kb + tx] = v;
        }
        return;
    }
    b -= NB_W2T;
    if (b < NB_GZ) {                                     // ---- zero G (split-K atomics) ----
        g_G[b * 256 + tid] = 0.0f;
        return;
    }
    // ---- bw2 = ba @ W2 (1 block) ----
    int c = tid & 63, sl = tid >> 6;
    float acc = 0.0f;
    for (int d = sl * 1024; d < (sl + 1) * 1024; d++) acc += ba[d] * W2[d * NC + c];
    red[tid] = acc;
    __syncthreads();
    if (sl == 0) g_bw2[c] = red[c] + red[c + 64] + red[c + 128] + red[c + 192];
}

__global__ void k_fillB(const float* __restrict__ att) {
    size_t i = (size_t)blockIdx.x * 256 + threadIdx.x;    // NH*BR*HD
    if (i >= (size_t)NH * BR * HD) return;
    int d = (int)(i & (HD - 1));
    int rh = (int)(i >> 12);
    int r = rh % BR, h = rh / BR;
    float v;
    if (r < 64)       v = g_W2T[(size_t)r * HD + d];
    else if (r == 64) v = tf32r(att[h * 2 * HD + d]);
    else if (r == 65) v = tf32r(att[h * 2 * HD + HD + d]);
    else              v = 0.0f;
    g_Ball[i] = v;
}

// ---------------- fused CSR: per-warp count + offset + place (deterministic) ----------------
__global__ void __launch_bounds__(256) k_csr(const int* __restrict__ edge) {
    __shared__ int se_[NNZ];
    int tid = threadIdx.x;
    for (int i = tid; i < NNZ; i += 256) se_[i] = edge[i];
    __syncthreads();
    int lane = tid & 31;
    int e = blockIdx.x * 8 + (tid >> 5);
    int nlt = 0, cnt = 0;
    for (int i = lane; i < NNZ; i += 32) {
        int v = se_[i];
        nlt += __popc(__ballot_sync(0xFFFFFFFFu, v < e));
        cnt += __popc(__ballot_sync(0xFFFFFFFFu, v == e));
    }
    int w = nlt;
    for (int i = lane; i < NNZ; i += 32) {
        int v = se_[i];
        unsigned m = __ballot_sync(0xFFFFFFFFu, v == e);
        if (v == e)
            g_csr[w + __popc(m & ((1u << lane) - 1u))] = i;
        w += __popc(m);
    }
    if (lane == 0) {
        g_bcnt[e] = cnt;
        g_boff[e] = nlt;
        g_Binv[e] = (cnt > 0) ? 1.0f / (float)cnt : 0.0f;
    }
}

// ---------------- hgc1 gathers (float4) ----------------
__global__ void __launch_bounds__(256) k_edgefeat() {
    int e = blockIdx.x;
    int d4 = blockIdx.y * 256 + threadIdx.x;
    int off = g_boff[e], cnt = g_bcnt[e];
    float4 acc = make_float4(0.f, 0.f, 0.f, 0.f);
    const float4* xl4 = (const float4*)g_xl;
    for (int t = 0; t < cnt; t++) {
        int i = g_csr[off + t];
        float4 v = xl4[(size_t)(i >> 3) * (HD / 4) + d4];
        acc.x += v.x; acc.y += v.y; acc.z += v.z; acc.w += v.w;
    }
    float bi = g_Binv[e];
    acc.x *= bi; acc.y *= bi; acc.z *= bi; acc.w *= bi;
    ((float4*)g_ef)[(size_t)e * (HD / 4) + d4] = acc;
}
__global__ void __launch_bounds__(256) k_feat(const int* __restrict__ edge,
                                              const float* __restrict__ b1,
                                              float* __restrict__ feat) {
    int n = blockIdx.x;
    int d4 = blockIdx.y * 256 + threadIdx.x;
    float4 acc = make_float4(0.f, 0.f, 0.f, 0.f);
    const float4* ef4 = (const float4*)g_ef;
#pragma unroll
    for (int j = 0; j < KD; j++) {
        int e = edge[n * KD + j];
        float4 v = ef4[(size_t)e * (HD / 4) + d4];
        acc.x += v.x; acc.y += v.y; acc.z += v.z; acc.w += v.w;
    }
    float4 bb = ((const float4*)b1)[d4];
    float4 r, rc;
    r.x = fmaxf(acc.x * DINV + bb.x, 0.f);
    r.y = fmaxf(acc.y * DINV + bb.y, 0.f);
    r.z = fmaxf(acc.z * DINV + bb.z, 0.f);
    r.w = fmaxf(acc.w * DINV + bb.w, 0.f);
    rc.x = tf32r(r.x); rc.y = tf32r(r.y); rc.z = tf32r(r.z); rc.w = tf32r(r.w);
    ((float4*)feat)[(size_t)n * (HD / 4) + d4] = r;       // exact output #1
    ((float4*)g_featc)[(size_t)n * (HD / 4) + d4] = rc;   // rounded A for G gemm
}
__global__ void __launch_bounds__(256) k_he(const float* __restrict__ feat) {
    int e = blockIdx.x;
    int d4 = blockIdx.y * 256 + threadIdx.x;
    int off = g_boff[e], cnt = g_bcnt[e];
    float4 acc = make_float4(0.f, 0.f, 0.f, 0.f);
    const float4* f4 = (const float4*)feat;
    for (int t = 0; t < cnt; t++) {
        int i = g_csr[off + t];
        float4 v = f4[(size_t)(i >> 3) * (HD / 4) + d4];
        acc.x += v.x; acc.y += v.y; acc.z += v.z; acc.w += v.w;
    }
    float inv = 1.0f / (float)cnt;
    acc.x *= inv; acc.y *= inv; acc.z *= inv; acc.w *= inv;
    ((float4*)g_he)[(size_t)e * (HD / 4) + d4] = acc;
}

// ---------------- attention logits + softmax ----------------
__global__ void __launch_bounds__(256) k_sxse(const float* __restrict__ feat) {
    int b = blockIdx.x;
    const float* row; const float* V; float* out;
    if (b < NN) { row = feat + (size_t)b * HD; V = g_V1; out = g_sx + b * NH; }
    else { int e = b - NN; row = g_he + (size_t)e * HD; V = g_V2; out = g_se + e * NH; }
    float acc[NH] = {};
    for (int k = threadIdx.x; k < HD; k += 256) {
        float xv = row[k];
        float4 w0 = *(const float4*)&V[k * NH];
        float4 w1 = *(const float4*)&V[k * NH + 4];
        acc[0] += xv * w0.x; acc[1] += xv * w0.y; acc[2] += xv * w0.z; acc[3] += xv * w0.w;
        acc[4] += xv * w1.x; acc[5] += xv * w1.y; acc[6] += xv * w1.z; acc[7] += xv * w1.w;
    }
    __shared__ float red[NH][256];
#pragma unroll
    for (int h = 0; h < NH; h++) red[h][threadIdx.x] = acc[h];
    __syncthreads();
    for (int s = 128; s > 0; s >>= 1) {
        if (threadIdx.x < s) {
#pragma unroll
            for (int h = 0; h < NH; h++) red[h][threadIdx.x] += red[h][threadIdx.x + s];
        }
        __syncthreads();
    }
    if (threadIdx.x < NH) out[threadIdx.x] = red[threadIdx.x][0];
}
__global__ void k_alpha(const int* __restrict__ edge) {
    int id = blockIdx.x * blockDim.x + threadIdx.x;
    if (id >= NN * NH) return;
    int n = id >> 3, h = id & 7;
    float sxv = g_sx[n * NH + h];
    float l[KD];
    float m = -1e30f;
#pragma unroll
    for (int j = 0; j < KD; j++) {
        int e = edge[n * KD + j];
        float t = sxv + g_se[e * NH + h];
        t = t > 0.0f ? t : 0.2f * t;
        l[j] = t;
        m = fmaxf(m, t);
    }
    float s = 0.0f;
#pragma unroll
    for (int j = 0; j < KD; j++) { l[j] = expf(l[j] - m); s += l[j]; }
    float inv = 1.0f / s;
#pragma unroll
    for (int j = 0; j < KD; j++) g_alpha[(n * KD + j) * NH + h] = l[j] * inv;
}

// ---------------- CODE-space aggregation ----------------
__global__ void __launch_bounds__(256) k_R() {
    int e = blockIdx.x;
    int hc = blockIdx.y * 256 + threadIdx.x;
    int h = hc >> 6;
    int off = g_boff[e], cnt = g_bcnt[e];
    float acc = 0.0f;
    for (int t = 0; t < cnt; t++) {
        int i = g_csr[off + t];
        acc += g_alpha[i * NH + h] * g_G[(i >> 3) * GC + hc];
    }
    g_R[e * HC + hc] = acc * g_Binv[e];
}
__global__ void k_Y(const int* __restrict__ edge) {
    int n = blockIdx.x, c = threadIdx.x;
    float acc = g_G[n * GC + HC + c] + g_bw2[c];
    float s = 0.0f;
#pragma unroll
    for (int j = 0; j < KD; j++) {
        int e = edge[n * KD + j];
        const float* al = &g_alpha[(n * KD + j) * NH];
        const float* Rr = &g_R[e * HC + c];
#pragma unroll
        for (int h = 0; h < NH; h++) s += al[h] * Rr[h * NC];
    }
    g_Y[n * NC + c] = acc + s * DINV * (1.0f / NH);
}
__global__ void k_ef2() {
    int e = blockIdx.x, c = threadIdx.x;
    int off = g_boff[e], cnt = g_bcnt[e];
    float acc = 0.0f;
    for (int t = 0; t < cnt; t++) {
        int i = g_csr[off + t];
        acc += g_Y[(i >> 3) * NC + c];
    }
    g_ef2[e * NC + c] = acc * g_Binv[e];
}
__global__ void k_out(const int* __restrict__ edge, const float* __restrict__ b2,
                      float* __restrict__ out) {
    int n = blockIdx.x, c = threadIdx.x;
    float acc = 0.0f;
#pragma unroll
    for (int j = 0; j < KD; j++) {
        int e = edge[n * KD + j];
        acc += g_ef2[e * NC + c];
    }
    float hid = acc * DINV + b2[c];
    out[(size_t)NN * HD + n * NC + c] = hid;
    out[(size_t)NN * HD + NN * NC + n * NC + c] = tanhf(hid);
}

// ---------------- launch ----------------
extern "C" void kernel_launch(void* const* d_in, const int* in_sizes, int n_in,
                              void* d_out, int out_size) {
    const float* x    = (const float*)d_in[0];
    const int*   edge = (const int*)  d_in[2];
    const float* W1   = (const float*)d_in[3];
    const float* b1   = (const float*)d_in[4];
    const float* Wa   = (const float*)d_in[5];
    const float* att  = (const float*)d_in[6];
    const float* ba   = (const float*)d_in[7];
    const float* W2   = (const float*)d_in[8];
    const float* b2   = (const float*)d_in[9];
    float* out  = (float*)d_out;
    float* feat = out;

    // idempotent attribute sets (host-side, graph-capture safe)
    cudaFuncSetAttribute(k_tgMV, cudaFuncAttributeMaxDynamicSharedMemorySize, SMEM_MV);
    cudaFuncSetAttribute(k_tg1,  cudaFuncAttributeMaxDynamicSharedMemorySize, SMEM_T1);
    cudaFuncSetAttribute(k_tgG,  cudaFuncAttributeMaxDynamicSharedMemorySize, SMEM_GG);

    k_csr<<<64, 256>>>(edge);                                         // 1
    k_prepA<<<NB_XPAD + NB_W1T + NB_W2T + NB_GZ + 1, 256>>>(x, W1, W2, ba); // 2
    k_fillB<<<(NH * BR * HD + 255) / 256, 256>>>(att);                // 3
    k_tgMV<<<dim3(32, 8), 256, SMEM_MV>>>(Wa);                        // 4  <- ncu slot
    k_tg1<<<dim3(4, 64), 256, SMEM_T1>>>();                           // 5
    k_edgefeat<<<dim3(EE, 4), 256>>>();                               // 6
    k_feat<<<dim3(NN, 4), 256>>>(edge, b1, feat);                     // 7
    k_he<<<dim3(EE, 4), 256>>>(feat);                                 // 8
    k_sxse<<<NN + EE, 256>>>(feat);                                   // 9
    k_alpha<<<16, 256>>>(edge);                                       // 10
    k_tgG<<<dim3(4, 18, 2), 256, SMEM_GG>>>();                        // 11
    k_R<<<dim3(EE, 2), 256>>>();                                      // 12
    k_Y<<<NN, 64>>>(edge);                                            // 13
    k_ef2<<<EE, 64>>>();                                              // 14
    k_out<<<NN, 64>>>(edge, b2, out);                                 // 15
}

// round 12
// speedup vs baseline: 1.0560x; 1.0222x over previous
#include <cuda_runtime.h>
#include <math.h>
#include <stdint.h>

#define NN   512        // nodes
#define KD   8          // edges per node
#define NNZ  4096       // incidences
#define FT   1386       // text features
#define FTP  1408       // padded to 32-multiple
#define HD   4096       // hidden
#define NH   8          // heads
#define NC   64         // code
#define EE   512        // hyperedges
#define HC   (NH*NC)    // 512
#define GC   (HC+NC)    // 576
#define WAC  (NH*HD)    // 32768
#define DINV 0.125f     // node degree is exactly KD=8 by construction

// ---------------- scratch (static device memory) ----------------
__device__ float g_xpad[NN*FTP];      // tf32-rounded x, padded
__device__ float g_W1T[HD*FTP];       // tf32-rounded W1^T
__device__ float g_W2T[NC*HD];        // tf32-rounded W2^T (also B of MV gemm)
__device__ float g_BcatT[GC*HD];      // rows 0..511 = M^T; 512..575 = W2T
__device__ float g_xl[NN*HD];
__device__ float g_ef[EE*HD];
__device__ float g_he[EE*HD];
__device__ float g_featc[NN*HD];      // tf32-rounded feat (A of G gemm)
__device__ float g_V1[HD*NH];
__device__ float g_V2[HD*NH];
__device__ float g_sx[NN*NH];
__device__ float g_se[EE*NH];
__device__ float g_alpha[NNZ*NH];
__device__ float g_G[NN*GC];
__device__ float g_R[EE*HC];
__device__ float g_Y[NN*NC];
__device__ float g_ef2[EE*NC];
__device__ float g_bw2[NC];
__device__ int   g_bcnt[EE];
__device__ int   g_boff[EE];
__device__ int   g_csr[NNZ];
__device__ float g_Binv[EE];

// ---------------- helpers ----------------
__device__ __forceinline__ float tf32r(float x) {
    float y;
    asm("cvt.rna.tf32.f32 %0, %1;" : "=f"(y) : "f"(x));
    return y;
}
__device__ __forceinline__ uint32_t smem_u32(const void* p) {
    uint32_t a;
    asm("{ .reg .u64 t; cvta.to.shared.u64 t, %1; cvt.u32.u64 %0, t; }" : "=r"(a) : "l"(p));
    return a;
}
#define CP_ASYNC16(dst, src) \
    asm volatile("cp.async.cg.shared.global [%0], [%1], 16;" :: "r"(dst), "l"(src))
#define CP_COMMIT() asm volatile("cp.async.commit_group;" ::: "memory")
#define CP_WAIT2()  asm volatile("cp.async.wait_group 2;" ::: "memory")
#define CP_WAIT1()  asm volatile("cp.async.wait_group 1;" ::: "memory")
#define CP_WAIT0()  asm volatile("cp.async.wait_group 0;" ::: "memory")

#define MMA_TF32(C, A0, A1, A2, A3, B0, B1) \
    asm volatile("mma.sync.aligned.m16n8k8.row.col.f32.tf32.tf32.f32 " \
        "{%0,%1,%2,%3},{%4,%5,%6,%7},{%8,%9},{%0,%1,%2,%3};" \
        : "+f"((C)[0]), "+f"((C)[1]), "+f"((C)[2]), "+f"((C)[3]) \
        : "r"(A0), "r"(A1), "r"(A2), "r"(A3), "r"(B0), "r"(B1))

__device__ __forceinline__ void ldsm4(uint32_t* r, uint32_t a) {
    asm volatile("ldmatrix.sync.aligned.m8n8.x4.shared.b16 {%0,%1,%2,%3}, [%4];"
        : "=r"(r[0]), "=r"(r[1]), "=r"(r[2]), "=r"(r[3]) : "r"(a));
}

#define ASTAGE_F (128*36)              // floats per A stage
#define ASTAGE_B (ASTAGE_F*4)          // bytes per A stage

// ============ tf32 mma.sync mainloop v4: 4-stage A, 2-stage B, optional V-FMA ============
// C[128 x BN] += A[128 x 32*NCH] * B[BN x 32*NCH]^T  (BN multiple of 32; NCH >= 4)
// WV: also accumulate v1/v2 = A-rows dot att1/att2 chunks (attg = att row base).
// smem: As[4 stages] | Bs[2 stages] | satt[2][2][32] (WV only)
template<int BN, int NCH, bool WV>
__device__ __forceinline__ void mma_v4(float* __restrict__ sm,
                                       const float* __restrict__ A, size_t lda,
                                       const float* __restrict__ B, size_t ldb,
                                       const float* __restrict__ attg,
                                       float (&acc)[2][BN/16][4],
                                       float (&v1)[2][2], float (&v2)[2][2]) {
    constexpr int NT = BN / 16;
    constexpr int PBN = (BN * 16) / 256;       // float2 B loads per thread
    constexpr int BSTAGE_F = BN * 36;
    float* Bs_ = sm + 4 * ASTAGE_F;
    float* sa  = sm + 4 * ASTAGE_F + 2 * BSTAGE_F;   // [2][64]
    const int tid = threadIdx.x, lane = tid & 31, wid = tid >> 5;
    const int wm = wid >> 1, wn = wid & 1;
    const int ar = tid >> 3, ac = (tid & 7) * 4;
    const int sub = lane >> 3, l7 = lane & 7;
    const int fq = lane & 3;
    const uint32_t aBase = smem_u32(sm);
    const uint32_t bBase = smem_u32(Bs_);
    float2 pb[PBN];
    float patt = 0.0f;

    uint32_t aAddr[2];
#pragma unroll
    for (int mt = 0; mt < 2; mt++)
        aAddr[mt] = aBase + (uint32_t)(((wm * 32 + mt * 16 + l7 + (sub & 1) * 8) * 36) * 4)
                  + (uint32_t)((sub >> 1) * 16);
    uint32_t bAddr[NT / 2];
#pragma unroll
    for (int p = 0; p < NT / 2; p++)
        bAddr[p] = bBase + (uint32_t)(((wn * (BN / 2) + p * 16 + l7 + (sub >> 1) * 8) * 36) * 4)
                 + (uint32_t)((sub & 1) * 16);

    // prologue: A chunks 0..2; B chunk 0 + att chunk 0 into regs
#pragma unroll
    for (int s = 0; s < 3; s++) {
        int d0 = s * 32;
        uint32_t sB = aBase + (uint32_t)s * ASTAGE_B;
#pragma unroll
        for (int p = 0; p < 4; p++) {
            uint32_t dst = sB + (uint32_t)(((ar + p * 32) * 36 + ac) * 4);
            CP_ASYNC16(dst, A + (size_t)(ar + p * 32) * lda + d0 + ac);
        }
        CP_COMMIT();
    }
#pragma unroll
    for (int p = 0; p < PBN; p++) {
        int idx = tid + p * 256;
        pb[p] = *(const float2*)&B[(size_t)(idx >> 4) * ldb + (idx & 15) * 2];
    }
    if (WV && tid < 64) patt = attg[(tid >> 5) * HD + (tid & 31)];

    for (int c = 0; c < NCH; c++) {
        if (c + 2 < NCH)      CP_WAIT2();
        else if (c + 1 < NCH) CP_WAIT1();
        else                  CP_WAIT0();
#pragma unroll
        for (int p = 0; p < PBN; p++) {
            int idx = tid + p * 256;
            *(float2*)&Bs_[(c & 1) * BSTAGE_F + (idx >> 4) * 36 + (idx & 15) * 2] = pb[p];
        }
        if (WV && tid < 64) sa[(c & 1) * 64 + tid] = patt;
        __syncthreads();
        if (c + 1 < NCH) {
            int d0 = (c + 1) * 32;
#pragma unroll
            for (int p = 0; p < PBN; p++) {
                int idx = tid + p * 256;
                pb[p] = *(const float2*)&B[(size_t)(idx >> 4) * ldb + d0 + (idx & 15) * 2];
            }
            if (WV && tid < 64) patt = attg[(tid >> 5) * HD + d0 + (tid & 31)];
        }
        if (c + 3 < NCH) {
            int d0 = (c + 3) * 32;
            uint32_t sB = aBase + (uint32_t)((c + 3) & 3) * ASTAGE_B;
#pragma unroll
            for (int p = 0; p < 4; p++) {
                uint32_t dst = sB + (uint32_t)(((ar + p * 32) * 36 + ac) * 4);
                CP_ASYNC16(dst, A + (size_t)(ar + p * 32) * lda + d0 + ac);
            }
            CP_COMMIT();
        }
        const uint32_t aS = (uint32_t)(c & 3) * ASTAGE_B;
        const uint32_t bS = (uint32_t)(c & 1) * (BSTAGE_F * 4);
        const float* sav = sa + (c & 1) * 64;
#pragma unroll
        for (int kk = 0; kk < 4; kk++) {
            uint32_t af[2][4];
            ldsm4(af[0], aAddr[0] + aS + kk * 32);
            ldsm4(af[1], aAddr[1] + aS + kk * 32);
            uint32_t bf[NT][2];
#pragma unroll
            for (int p = 0; p < NT / 2; p++) {
                uint32_t t[4];
                ldsm4(t, bAddr[p] + bS + kk * 32);
                bf[2 * p][0] = t[0]; bf[2 * p][1] = t[1];
                bf[2 * p + 1][0] = t[2]; bf[2 * p + 1][1] = t[3];
            }
            if (WV && wn == 0) {                      // V-FMA on the idle fma pipe
                int kc = kk * 8 + fq;
                float t1a = sav[kc], t1b = sav[kc + 4];
                float t2a = sav[32 + kc], t2b = sav[32 + kc + 4];
#pragma unroll
                for (int mt = 0; mt < 2; mt++) {
                    float a0 = __uint_as_float(af[mt][0]), a1 = __uint_as_float(af[mt][1]);
                    float a2 = __uint_as_float(af[mt][2]), a3 = __uint_as_float(af[mt][3]);
                    v1[mt][0] += a0 * t1a + a2 * t1b;
                    v1[mt][1] += a1 * t1a + a3 * t1b;
                    v2[mt][0] += a0 * t2a + a2 * t2b;
                    v2[mt][1] += a1 * t2a + a3 * t2b;
                }
            }
#pragma unroll
            for (int nt = 0; nt < NT; nt++)
#pragma unroll
                for (int mt = 0; mt < 2; mt++)
                    MMA_TF32(acc[mt][nt], af[mt][0], af[mt][1], af[mt][2], af[mt][3],
                             bf[nt][0], bf[nt][1]);
        }
    }
}

#define SMEM_MV (4*ASTAGE_B + 2*64*36*4 + 2*64*4)  // 92672
#define SMEM_T1 (4*ASTAGE_B + 2*64*36*4)           // 92160
#define SMEM_GG (4*ASTAGE_B + 2*32*36*4)           // 82944

// ---------------- GEMM kernels ----------------
__global__ void __launch_bounds__(256) k_tgMV(const float* __restrict__ Wa,
                                              const float* __restrict__ att) {
    extern __shared__ float dsm[];
    float acc[2][4][4] = {};
    float v1[2][2] = {}, v2[2][2] = {};
    int h = blockIdx.y;
    const float* A = Wa + (size_t)h * HD + (size_t)blockIdx.x * 128 * WAC;
    mma_v4<64, HD / 32, true>(dsm, A, WAC, g_W2T, HD, att + (size_t)h * 2 * HD,
                              acc, v1, v2);          // Wa operands tf32-truncated
    int lane = threadIdx.x & 31, wid = threadIdx.x >> 5;
    int wm = wid >> 1, wn = wid & 1;
    int fr = lane >> 2, fq = lane & 3;
    int k0 = blockIdx.x * 128 + wm * 32 + fr;
#pragma unroll
    for (int mt = 0; mt < 2; mt++) {
        int k = k0 + mt * 16;
#pragma unroll
        for (int nt = 0; nt < 4; nt++) {
            int n = wn * 32 + nt * 8 + fq * 2;
            g_BcatT[(size_t)(h * 64 + n) * HD + k]         = tf32r(acc[mt][nt][0]);
            g_BcatT[(size_t)(h * 64 + n + 1) * HD + k]     = tf32r(acc[mt][nt][1]);
            g_BcatT[(size_t)(h * 64 + n) * HD + k + 8]     = tf32r(acc[mt][nt][2]);
            g_BcatT[(size_t)(h * 64 + n + 1) * HD + k + 8] = tf32r(acc[mt][nt][3]);
        }
    }
    // V reduction: sum the 4 fq-lanes of each fr group (deterministic tree)
    if (wn == 0) {
#pragma unroll
        for (int mt = 0; mt < 2; mt++)
#pragma unroll
            for (int r8 = 0; r8 < 2; r8++) {
                float a = v1[mt][r8], b = v2[mt][r8];
                a += __shfl_xor_sync(0xFFFFFFFFu, a, 1);
                a += __shfl_xor_sync(0xFFFFFFFFu, a, 2);
                b += __shfl_xor_sync(0xFFFFFFFFu, b, 1);
                b += __shfl_xor_sync(0xFFFFFFFFu, b, 2);
                if (fq == 0) {
                    int k = k0 + mt * 16 + r8 * 8;
                    g_V1[k * NH + h] = a;
                    g_V2[k * NH + h] = b;
                }
            }
    }
}

__global__ void __launch_bounds__(256) k_tg1() {       // xl = xpad @ W1T^T
    extern __shared__ float dsm[];
    float acc[2][4][4] = {};
    float dv1[2][2], dv2[2][2];
    const float* A = g_xpad + (size_t)blockIdx.x * 128 * FTP;
    const float* B = g_W1T + (size_t)blockIdx.y * 64 * FTP;
    mma_v4<64, FTP / 32, false>(dsm, A, FTP, B, FTP, nullptr, acc, dv1, dv2);
    int lane = threadIdx.x & 31, wid = threadIdx.x >> 5;
    int rb = blockIdx.x * 128 + (wid >> 1) * 32 + (lane >> 2);
    int cb = blockIdx.y * 64 + (wid & 1) * 32 + 2 * (lane & 3);
#pragma unroll
    for (int mt = 0; mt < 2; mt++)
#pragma unroll
        for (int nt = 0; nt < 4; nt++) {
            int r = rb + mt * 16, cc = cb + nt * 8;
            *(float2*)&g_xl[(size_t)r * HD + cc] = make_float2(acc[mt][nt][0], acc[mt][nt][1]);
            *(float2*)&g_xl[(size_t)(r + 8) * HD + cc] = make_float2(acc[mt][nt][2], acc[mt][nt][3]);
        }
}

__global__ void __launch_bounds__(256) k_tgG() {       // G += featc @ BcatT^T (split-K 2)
    extern __shared__ float dsm[];
    float acc[2][2][4] = {};
    float dv1[2][2], dv2[2][2];
    int m0 = blockIdx.x * 128, n0 = blockIdx.y * 32, kz = blockIdx.z * 2048;
    const float* A = g_featc + (size_t)m0 * HD + kz;
    const float* B = g_BcatT + (size_t)n0 * HD + kz;
    mma_v4<32, 64, false>(dsm, A, HD, B, HD, nullptr, acc, dv1, dv2);
    int lane = threadIdx.x & 31, wid = threadIdx.x >> 5;
    int rb = m0 + (wid >> 1) * 32 + (lane >> 2);
    int cb = n0 + (wid & 1) * 16 + 2 * (lane & 3);
#pragma unroll
    for (int mt = 0; mt < 2; mt++)
#pragma unroll
        for (int nt = 0; nt < 2; nt++) {
            int r = rb + mt * 16, cc = cb + nt * 8;
            atomicAdd(&g_G[(size_t)r * GC + cc],           acc[mt][nt][0]);
            atomicAdd(&g_G[(size_t)r * GC + cc + 1],       acc[mt][nt][1]);
            atomicAdd(&g_G[(size_t)(r + 8) * GC + cc],     acc[mt][nt][2]);
            atomicAdd(&g_G[(size_t)(r + 8) * GC + cc + 1], acc[mt][nt][3]);
        }
}

// ---------------- fused prep: xpad | W1T | W2T(+BcatT tail) | zero-G | bw2 ----------------
#define NB_XPAD (NN*FTP/256)          // 2816
#define NB_W1T  ((FTP/32)*(HD/32))    // 5632
#define NB_W2T  ((HD/32)*(NC/32))     // 256
#define NB_GZ   (NN*GC/256)           // 1152
__global__ void __launch_bounds__(256) k_prepA(const float* __restrict__ x,
                                               const float* __restrict__ W1,
                                               const float* __restrict__ W2,
                                               const float* __restrict__ ba) {
    __shared__ float t[32][33];
    __shared__ float red[256];
    int b = blockIdx.x, tid = threadIdx.x;
    if (b < NB_XPAD) {                                   // ---- xpad ----
        int i = b * 256 + tid;
        int r = i / FTP, c = i % FTP;
        g_xpad[i] = (c < FT) ? tf32r(x[r * FT + c]) : 0.0f;
        return;
    }
    b -= NB_XPAD;
    if (b < NB_W1T) {                                    // ---- W1T transpose ----
        int ky = b / (HD / 32), nx = b % (HD / 32);
        int kb = ky * 32, nb = nx * 32;
        int tx = tid & 31, ty = tid >> 5;
        for (int i = ty; i < 32; i += 8) {
            int k = kb + i;
            t[i][tx] = (k < FT) ? tf32r(W1[(size_t)k * HD + nb + tx]) : 0.0f;
        }
        __syncthreads();
        for (int i = ty; i < 32; i += 8)
            g_W1T[(size_t)(nb + i) * FTP + kb + tx] = t[tx][i];
        return;
    }
    b -= NB_W1T;
    if (b < NB_W2T) {                                    // ---- W2T + BcatT tail ----
        int kb = (b >> 1) * 32, nb = (b & 1) * 32;
        int tx = tid & 31, ty = tid >> 5;
        for (int i = ty; i < 32; i += 8)
            t[i][tx] = tf32r(W2[(size_t)(kb + i) * NC + nb + tx]);
        __syncthreads();
        for (int i = ty; i < 32; i += 8) {
            float v = t[tx][i];
            g_W2T[(size_t)(nb + i) * HD + kb + tx] = v;
            g_BcatT[(size_t)(HC + nb + i) * HD + kb + tx] = v;
        }
        return;
    }
    b -= NB_W2T;
    if (b < NB_GZ) {                                     // ---- zero G (split-K atomics) ----
        g_G[b * 256 + tid] = 0.0f;
        return;
    }
    // ---- bw2 = ba @ W2 (1 block) ----
    int c = tid & 63, sl = tid >> 6;
    float acc = 0.0f;
    for (int d = sl * 1024; d < (sl + 1) * 1024; d++) acc += ba[d] * W2[d * NC + c];
    red[tid] = acc;
    __syncthreads();
    if (sl == 0) g_bw2[c] = red[c] + red[c + 64] + red[c + 128] + red[c + 192];
}

// ---------------- fused CSR: per-warp count + offset + place (deterministic) ----------------
__global__ void __launch_bounds__(256) k_csr(const int* __restrict__ edge) {
    __shared__ int se_[NNZ];
    int tid = threadIdx.x;
    for (int i = tid; i < NNZ; i += 256) se_[i] = edge[i];
    __syncthreads();
    int lane = tid & 31;
    int e = blockIdx.x * 8 + (tid >> 5);
    int nlt = 0, cnt = 0;
    for (int i = lane; i < NNZ; i += 32) {
        int v = se_[i];
        nlt += __popc(__ballot_sync(0xFFFFFFFFu, v < e));
        cnt += __popc(__ballot_sync(0xFFFFFFFFu, v == e));
    }
    int w = nlt;
    for (int i = lane; i < NNZ; i += 32) {
        int v = se_[i];
        unsigned m = __ballot_sync(0xFFFFFFFFu, v == e);
        if (v == e)
            g_csr[w + __popc(m & ((1u << lane) - 1u))] = i;
        w += __popc(m);
    }
    if (lane == 0) {
        g_bcnt[e] = cnt;
        g_boff[e] = nlt;
        g_Binv[e] = (cnt > 0) ? 1.0f / (float)cnt : 0.0f;
    }
}

// ---------------- hgc1 gathers (float4) ----------------
__global__ void __launch_bounds__(256) k_edgefeat() {
    int e = blockIdx.x;
    int d4 = blockIdx.y * 256 + threadIdx.x;
    int off = g_boff[e], cnt = g_bcnt[e];
    float4 acc = make_float4(0.f, 0.f, 0.f, 0.f);
    const float4* xl4 = (const float4*)g_xl;
    for (int t = 0; t < cnt; t++) {
        int i = g_csr[off + t];
        float4 v = xl4[(size_t)(i >> 3) * (HD / 4) + d4];
        acc.x += v.x; acc.y += v.y; acc.z += v.z; acc.w += v.w;
    }
    float bi = g_Binv[e];
    acc.x *= bi; acc.y *= bi; acc.z *= bi; acc.w *= bi;
    ((float4*)g_ef)[(size_t)e * (HD / 4) + d4] = acc;
}
__global__ void __launch_bounds__(256) k_feat(const int* __restrict__ edge,
                                              const float* __restrict__ b1,
                                              float* __restrict__ feat) {
    int n = blockIdx.x;
    int d4 = blockIdx.y * 256 + threadIdx.x;
    float4 acc = make_float4(0.f, 0.f, 0.f, 0.f);
    const float4* ef4 = (const float4*)g_ef;
#pragma unroll
    for (int j = 0; j < KD; j++) {
        int e = edge[n * KD + j];
        float4 v = ef4[(size_t)e * (HD / 4) + d4];
        acc.x += v.x; acc.y += v.y; acc.z += v.z; acc.w += v.w;
    }
    float4 bb = ((const float4*)b1)[d4];
    float4 r, rc;
    r.x = fmaxf(acc.x * DINV + bb.x, 0.f);
    r.y = fmaxf(acc.y * DINV + bb.y, 0.f);
    r.z = fmaxf(acc.z * DINV + bb.z, 0.f);
    r.w = fmaxf(acc.w * DINV + bb.w, 0.f);
    rc.x = tf32r(r.x); rc.y = tf32r(r.y); rc.z = tf32r(r.z); rc.w = tf32r(r.w);
    ((float4*)feat)[(size_t)n * (HD / 4) + d4] = r;       // exact output #1
    ((float4*)g_featc)[(size_t)n * (HD / 4) + d4] = rc;   // rounded A for G gemm
}
__global__ void __launch_bounds__(256) k_he(const float* __restrict__ feat) {
    int e = blockIdx.x;
    int d4 = blockIdx.y * 256 + threadIdx.x;
    int off = g_boff[e], cnt = g_bcnt[e];
    float4 acc = make_float4(0.f, 0.f, 0.f, 0.f);
    const float4* f4 = (const float4*)feat;
    for (int t = 0; t < cnt; t++) {
        int i = g_csr[off + t];
        float4 v = f4[(size_t)(i >> 3) * (HD / 4) + d4];
        acc.x += v.x; acc.y += v.y; acc.z += v.z; acc.w += v.w;
    }
    float inv = 1.0f / (float)cnt;
    acc.x *= inv; acc.y *= inv; acc.z *= inv; acc.w *= inv;
    ((float4*)g_he)[(size_t)e * (HD / 4) + d4] = acc;
}

// ---------------- attention logits + softmax ----------------
__global__ void __launch_bounds__(256) k_sxse(const float* __restrict__ feat) {
    int b = blockIdx.x;
    const float* row; const float* V; float* out;
    if (b < NN) { row = feat + (size_t)b * HD; V = g_V1; out = g_sx + b * NH; }
    else { int e = b - NN; row = g_he + (size_t)e * HD; V = g_V2; out = g_se + e * NH; }
    float acc[NH] = {};
    for (int k = threadIdx.x; k < HD; k += 256) {
        float xv = row[k];
        float4 w0 = *(const float4*)&V[k * NH];
        float4 w1 = *(const float4*)&V[k * NH + 4];
        acc[0] += xv * w0.x; acc[1] += xv * w0.y; acc[2] += xv * w0.z; acc[3] += xv * w0.w;
        acc[4] += xv * w1.x; acc[5] += xv * w1.y; acc[6] += xv * w1.z; acc[7] += xv * w1.w;
    }
    __shared__ float red[NH][256];
#pragma unroll
    for (int h = 0; h < NH; h++) red[h][threadIdx.x] = acc[h];
    __syncthreads();
    for (int s = 128; s > 0; s >>= 1) {
        if (threadIdx.x < s) {
#pragma unroll
            for (int h = 0; h < NH; h++) red[h][threadIdx.x] += red[h][threadIdx.x + s];
        }
        __syncthreads();
    }
    if (threadIdx.x < NH) out[threadIdx.x] = red[threadIdx.x][0];
}
__global__ void k_alpha(const int* __restrict__ edge) {
    int id = blockIdx.x * blockDim.x + threadIdx.x;
    if (id >= NN * NH) return;
    int n = id >> 3, h = id & 7;
    float sxv = g_sx[n * NH + h];
    float l[KD];
    float m = -1e30f;
#pragma unroll
    for (int j = 0; j < KD; j++) {
        int e = edge[n * KD + j];
        float t = sxv + g_se[e * NH + h];
        t = t > 0.0f ? t : 0.2f * t;
        l[j] = t;
        m = fmaxf(m, t);
    }
    float s = 0.0f;
#pragma unroll
    for (int j = 0; j < KD; j++) { l[j] = expf(l[j] - m); s += l[j]; }
    float inv = 1.0f / s;
#pragma unroll
    for (int j = 0; j < KD; j++) g_alpha[(n * KD + j) * NH + h] = l[j] * inv;
}

// ---------------- CODE-space aggregation ----------------
__global__ void __launch_bounds__(256) k_R() {
    int e = blockIdx.x;
    int hc = blockIdx.y * 256 + threadIdx.x;
    int h = hc >> 6;
    int off = g_boff[e], cnt = g_bcnt[e];
    float acc = 0.0f;
    for (int t = 0; t < cnt; t++) {
        int i = g_csr[off + t];
        acc += g_alpha[i * NH + h] * g_G[(i >> 3) * GC + hc];
    }
    g_R[e * HC + hc] = acc * g_Binv[e];
}
__global__ void k_Y(const int* __restrict__ edge) {
    int n = blockIdx.x, c = threadIdx.x;
    float acc = g_G[n * GC + HC + c] + g_bw2[c];
    float s = 0.0f;
#pragma unroll
    for (int j = 0; j < KD; j++) {
        int e = edge[n * KD + j];
        const float* al = &g_alpha[(n * KD + j) * NH];
        const float* Rr = &g_R[e * HC + c];
#pragma unroll
        for (int h = 0; h < NH; h++) s += al[h] * Rr[h * NC];
    }
    g_Y[n * NC + c] = acc + s * DINV * (1.0f / NH);
}
__global__ void k_ef2() {
    int e = blockIdx.x, c = threadIdx.x;
    int off = g_boff[e], cnt = g_bcnt[e];
    float acc = 0.0f;
    for (int t = 0; t < cnt; t++) {
        int i = g_csr[off + t];
        acc += g_Y[(i >> 3) * NC + c];
    }
    g_ef2[e * NC + c] = acc * g_Binv[e];
}
__global__ void k_out(const int* __restrict__ edge, const float* __restrict__ b2,
                      float* __restrict__ out) {
    int n = blockIdx.x, c = threadIdx.x;
    float acc = 0.0f;
#pragma unroll
    for (int j = 0; j < KD; j++) {
        int e = edge[n * KD + j];
        acc += g_ef2[e * NC + c];
    }
    float hid = acc * DINV + b2[c];
    out[(size_t)NN * HD + n * NC + c] = hid;
    out[(size_t)NN * HD + NN * NC + n * NC + c] = tanhf(hid);
}

// ---------------- launch ----------------
extern "C" void kernel_launch(void* const* d_in, const int* in_sizes, int n_in,
                              void* d_out, int out_size) {
    const float* x    = (const float*)d_in[0];
    const int*   edge = (const int*)  d_in[2];
    const float* W1   = (const float*)d_in[3];
    const float* b1   = (const float*)d_in[4];
    const float* Wa   = (const float*)d_in[5];
    const float* att  = (const float*)d_in[6];
    const float* ba   = (const float*)d_in[7];
    const float* W2   = (const float*)d_in[8];
    const float* b2   = (const float*)d_in[9];
    float* out  = (float*)d_out;
    float* feat = out;

    cudaFuncSetAttribute(k_tgMV, cudaFuncAttributeMaxDynamicSharedMemorySize, SMEM_MV);
    cudaFuncSetAttribute(k_tg1,  cudaFuncAttributeMaxDynamicSharedMemorySize, SMEM_T1);
    cudaFuncSetAttribute(k_tgG,  cudaFuncAttributeMaxDynamicSharedMemorySize, SMEM_GG);

    k_csr<<<64, 256>>>(edge);                                         // 1
    k_prepA<<<NB_XPAD + NB_W1T + NB_W2T + NB_GZ + 1, 256>>>(x, W1, W2, ba); // 2
    k_tgMV<<<dim3(32, 8), 256, SMEM_MV>>>(Wa, att);                   // 3
    k_tg1<<<dim3(4, 64), 256, SMEM_T1>>>();                           // 4
    k_edgefeat<<<dim3(EE, 4), 256>>>();                               // 5
    k_feat<<<dim3(NN, 4), 256>>>(edge, b1, feat);                     // 6
    k_he<<<dim3(EE, 4), 256>>>(feat);                                 // 7
    k_sxse<<<NN + EE, 256>>>(feat);                                   // 8
    k_alpha<<<16, 256>>>(edge);                                       // 9
    k_tgG<<<dim3(4, 18, 2), 256, SMEM_GG>>>();                        // 10
    k_R<<<dim3(EE, 2), 256>>>();                                      // 11
    k_Y<<<NN, 64>>>(edge);                                            // 12
    k_ef2<<<EE, 64>>>();                                              // 13
    k_out<<<NN, 64>>>(edge, b2, out);                                 // 14
}

// round 13
// speedup vs baseline: 1.1374x; 1.0771x over previous
#include <cuda_runtime.h>
#include <math.h>
#include <stdint.h>

#define NN   512        // nodes
#define KD   8          // edges per node
#define NNZ  4096       // incidences
#define FT   1386       // text features
#define FTP  1408       // padded to 32-multiple
#define HD   4096       // hidden
#define NH   8          // heads
#define NC   64         // code
#define EE   512        // hyperedges
#define HC   (NH*NC)    // 512
#define GC   (HC+NC)    // 576
#define WAC  (NH*HD)    // 32768
#define DINV 0.125f     // node degree is exactly KD=8 by construction

// ---------------- scratch (static device memory) ----------------
__device__ float g_xpad[NN*FTP];      // tf32-rounded x, padded
__device__ float g_W1T[HD*FTP];       // tf32-rounded W1^T
__device__ float g_W2T[NC*HD];        // tf32-rounded W2^T (also B of MV gemm)
__device__ float g_BcatT[GC*HD];      // rows 0..511 = M^T; 512..575 = W2T
__device__ float g_xl[NN*HD];
__device__ float g_ef[EE*HD];
__device__ float g_featc[NN*HD];      // tf32-rounded feat (A of G gemm)
__device__ float g_V1[HD*NH];
__device__ float g_V2[HD*NH];
__device__ float g_sx[NN*NH];
__device__ float g_s2n[NN*NH];        // per-node feat . V2
__device__ float g_se[EE*NH];
__device__ float g_alpha[NNZ*NH];
__device__ float g_G[NN*GC];
__device__ float g_R[EE*HC];
__device__ float g_Y[NN*NC];
__device__ float g_ef2[EE*NC];
__device__ float g_bw2[NC];
__device__ int   g_bcnt[EE];
__device__ int   g_boff[EE];
__device__ int   g_csr[NNZ];
__device__ float g_Binv[EE];

// ---------------- helpers ----------------
__device__ __forceinline__ float tf32r(float x) {
    float y;
    asm("cvt.rna.tf32.f32 %0, %1;" : "=f"(y) : "f"(x));
    return y;
}
__device__ __forceinline__ uint32_t smem_u32(const void* p) {
    uint32_t a;
    asm("{ .reg .u64 t; cvta.to.shared.u64 t, %1; cvt.u32.u64 %0, t; }" : "=r"(a) : "l"(p));
    return a;
}
#define CP_ASYNC16(dst, src) \
    asm volatile("cp.async.cg.shared.global [%0], [%1], 16;" :: "r"(dst), "l"(src))
#define CP_COMMIT() asm volatile("cp.async.commit_group;" ::: "memory")
#define CP_WAIT2()  asm volatile("cp.async.wait_group 2;" ::: "memory")
#define CP_WAIT1()  asm volatile("cp.async.wait_group 1;" ::: "memory")
#define CP_WAIT0()  asm volatile("cp.async.wait_group 0;" ::: "memory")

#define MMA_TF32(C, A0, A1, A2, A3, B0, B1) \
    asm volatile("mma.sync.aligned.m16n8k8.row.col.f32.tf32.tf32.f32 " \
        "{%0,%1,%2,%3},{%4,%5,%6,%7},{%8,%9},{%0,%1,%2,%3};" \
        : "+f"((C)[0]), "+f"((C)[1]), "+f"((C)[2]), "+f"((C)[3]) \
        : "r"(A0), "r"(A1), "r"(A2), "r"(A3), "r"(B0), "r"(B1))

__device__ __forceinline__ void ldsm4(uint32_t* r, uint32_t a) {
    asm volatile("ldmatrix.sync.aligned.m8n8.x4.shared.b16 {%0,%1,%2,%3}, [%4];"
        : "=r"(r[0]), "=r"(r[1]), "=r"(r[2]), "=r"(r[3]) : "r"(a));
}

#define ASTAGE_F (128*36)              // floats per A stage
#define ASTAGE_B (ASTAGE_F*4)          // bytes per A stage

// ============ tf32 mma.sync mainloop v4: 4-stage A, 2-stage B, optional V-FMA ============
template<int BN, int NCH, bool WV>
__device__ __forceinline__ void mma_v4(float* __restrict__ sm,
                                       const float* __restrict__ A, size_t lda,
                                       const float* __restrict__ B, size_t ldb,
                                       const float* __restrict__ attg,
                                       float (&acc)[2][BN/16][4],
                                       float (&v1)[2][2], float (&v2)[2][2]) {
    constexpr int NT = BN / 16;
    constexpr int PBN = (BN * 16) / 256;
    constexpr int BSTAGE_F = BN * 36;
    float* Bs_ = sm + 4 * ASTAGE_F;
    float* sa  = sm + 4 * ASTAGE_F + 2 * BSTAGE_F;   // [2][64]
    const int tid = threadIdx.x, lane = tid & 31, wid = tid >> 5;
    const int wm = wid >> 1, wn = wid & 1;
    const int ar = tid >> 3, ac = (tid & 7) * 4;
    const int sub = lane >> 3, l7 = lane & 7;
    const int fq = lane & 3;
    const uint32_t aBase = smem_u32(sm);
    const uint32_t bBase = smem_u32(Bs_);
    float2 pb[PBN];
    float patt = 0.0f;

    uint32_t aAddr[2];
#pragma unroll
    for (int mt = 0; mt < 2; mt++)
        aAddr[mt] = aBase + (uint32_t)(((wm * 32 + mt * 16 + l7 + (sub & 1) * 8) * 36) * 4)
                  + (uint32_t)((sub >> 1) * 16);
    uint32_t bAddr[NT / 2];
#pragma unroll
    for (int p = 0; p < NT / 2; p++)
        bAddr[p] = bBase + (uint32_t)(((wn * (BN / 2) + p * 16 + l7 + (sub >> 1) * 8) * 36) * 4)
                 + (uint32_t)((sub & 1) * 16);

#pragma unroll
    for (int s = 0; s < 3; s++) {
        int d0 = s * 32;
        uint32_t sB = aBase + (uint32_t)s * ASTAGE_B;
#pragma unroll
        for (int p = 0; p < 4; p++) {
            uint32_t dst = sB + (uint32_t)(((ar + p * 32) * 36 + ac) * 4);
            CP_ASYNC16(dst, A + (size_t)(ar + p * 32) * lda + d0 + ac);
        }
        CP_COMMIT();
    }
#pragma unroll
    for (int p = 0; p < PBN; p++) {
        int idx = tid + p * 256;
        pb[p] = *(const float2*)&B[(size_t)(idx >> 4) * ldb + (idx & 15) * 2];
    }
    if (WV && tid < 64) patt = attg[(tid >> 5) * HD + (tid & 31)];

    for (int c = 0; c < NCH; c++) {
        if (c + 2 < NCH)      CP_WAIT2();
        else if (c + 1 < NCH) CP_WAIT1();
        else                  CP_WAIT0();
#pragma unroll
        for (int p = 0; p < PBN; p++) {
            int idx = tid + p * 256;
            *(float2*)&Bs_[(c & 1) * BSTAGE_F + (idx >> 4) * 36 + (idx & 15) * 2] = pb[p];
        }
        if (WV && tid < 64) sa[(c & 1) * 64 + tid] = patt;
        __syncthreads();
        if (c + 1 < NCH) {
            int d0 = (c + 1) * 32;
#pragma unroll
            for (int p = 0; p < PBN; p++) {
                int idx = tid + p * 256;
                pb[p] = *(const float2*)&B[(size_t)(idx >> 4) * ldb + d0 + (idx & 15) * 2];
            }
            if (WV && tid < 64) patt = attg[(tid >> 5) * HD + d0 + (tid & 31)];
        }
        if (c + 3 < NCH) {
            int d0 = (c + 3) * 32;
            uint32_t sB = aBase + (uint32_t)((c + 3) & 3) * ASTAGE_B;
#pragma unroll
            for (int p = 0; p < 4; p++) {
                uint32_t dst = sB + (uint32_t)(((ar + p * 32) * 36 + ac) * 4);
                CP_ASYNC16(dst, A + (size_t)(ar + p * 32) * lda + d0 + ac);
            }
            CP_COMMIT();
        }
        const uint32_t aS = (uint32_t)(c & 3) * ASTAGE_B;
        const uint32_t bS = (uint32_t)(c & 1) * (BSTAGE_F * 4);
        const float* sav = sa + (c & 1) * 64;
#pragma unroll
        for (int kk = 0; kk < 4; kk++) {
            uint32_t af[2][4];
            ldsm4(af[0], aAddr[0] + aS + kk * 32);
            ldsm4(af[1], aAddr[1] + aS + kk * 32);
            uint32_t bf[NT][2];
#pragma unroll
            for (int p = 0; p < NT / 2; p++) {
                uint32_t t[4];
                ldsm4(t, bAddr[p] + bS + kk * 32);
                bf[2 * p][0] = t[0]; bf[2 * p][1] = t[1];
                bf[2 * p + 1][0] = t[2]; bf[2 * p + 1][1] = t[3];
            }
            if (WV && wn == 0) {
                int kc = kk * 8 + fq;
                float t1a = sav[kc], t1b = sav[kc + 4];
                float t2a = sav[32 + kc], t2b = sav[32 + kc + 4];
#pragma unroll
                for (int mt = 0; mt < 2; mt++) {
                    float a0 = __uint_as_float(af[mt][0]), a1 = __uint_as_float(af[mt][1]);
                    float a2 = __uint_as_float(af[mt][2]), a3 = __uint_as_float(af[mt][3]);
                    v1[mt][0] += a0 * t1a + a2 * t1b;
                    v1[mt][1] += a1 * t1a + a3 * t1b;
                    v2[mt][0] += a0 * t2a + a2 * t2b;
                    v2[mt][1] += a1 * t2a + a3 * t2b;
                }
            }
#pragma unroll
            for (int nt = 0; nt < NT; nt++)
#pragma unroll
                for (int mt = 0; mt < 2; mt++)
                    MMA_TF32(acc[mt][nt], af[mt][0], af[mt][1], af[mt][2], af[mt][3],
                             bf[nt][0], bf[nt][1]);
        }
    }
}

#define SMEM_MV (4*ASTAGE_B + 2*64*36*4 + 2*64*4)  // 92672
#define SMEM_T1 (4*ASTAGE_B + 2*64*36*4)           // 92160
#define SMEM_GG (4*ASTAGE_B + 2*32*36*4)           // 82944

// ---------------- k_tg1: xl = xpad @ W1T^T ----------------
__global__ void __launch_bounds__(256) k_tg1() {
    extern __shared__ float dsm[];
    float acc[2][4][4] = {};
    float dv1[2][2], dv2[2][2];
    const float* A = g_xpad + (size_t)blockIdx.x * 128 * FTP;
    const float* B = g_W1T + (size_t)blockIdx.y * 64 * FTP;
    mma_v4<64, FTP / 32, false>(dsm, A, FTP, B, FTP, nullptr, acc, dv1, dv2);
    int lane = threadIdx.x & 31, wid = threadIdx.x >> 5;
    int rb = blockIdx.x * 128 + (wid >> 1) * 32 + (lane >> 2);
    int cb = blockIdx.y * 64 + (wid & 1) * 32 + 2 * (lane & 3);
#pragma unroll
    for (int mt = 0; mt < 2; mt++)
#pragma unroll
        for (int nt = 0; nt < 4; nt++) {
            int r = rb + mt * 16, cc = cb + nt * 8;
            *(float2*)&g_xl[(size_t)r * HD + cc] = make_float2(acc[mt][nt][0], acc[mt][nt][1]);
            *(float2*)&g_xl[(size_t)(r + 8) * HD + cc] = make_float2(acc[mt][nt][2], acc[mt][nt][3]);
        }
}

// ---------------- k_mvef: blocks 0..255 tgMV, 256..767 edgefeat ----------------
__global__ void __launch_bounds__(256) k_mvef(const float* __restrict__ Wa,
                                              const float* __restrict__ att) {
    extern __shared__ float dsm[];
    int b = blockIdx.x;
    if (b < 256) {                                       // ---- tgMV ----
        float acc[2][4][4] = {};
        float v1[2][2] = {}, v2[2][2] = {};
        int h = b & 7, kxb = b >> 3;
        const float* A = Wa + (size_t)h * HD + (size_t)kxb * 128 * WAC;
        mma_v4<64, HD / 32, true>(dsm, A, WAC, g_W2T, HD, att + (size_t)h * 2 * HD,
                                  acc, v1, v2);
        int lane = threadIdx.x & 31, wid = threadIdx.x >> 5;
        int wm = wid >> 1, wn = wid & 1;
        int fr = lane >> 2, fq = lane & 3;
        int k0 = kxb * 128 + wm * 32 + fr;
#pragma unroll
        for (int mt = 0; mt < 2; mt++) {
            int k = k0 + mt * 16;
#pragma unroll
            for (int nt = 0; nt < 4; nt++) {
                int n = wn * 32 + nt * 8 + fq * 2;
                g_BcatT[(size_t)(h * 64 + n) * HD + k]         = tf32r(acc[mt][nt][0]);
                g_BcatT[(size_t)(h * 64 + n + 1) * HD + k]     = tf32r(acc[mt][nt][1]);
                g_BcatT[(size_t)(h * 64 + n) * HD + k + 8]     = tf32r(acc[mt][nt][2]);
                g_BcatT[(size_t)(h * 64 + n + 1) * HD + k + 8] = tf32r(acc[mt][nt][3]);
            }
        }
        if (wn == 0) {
#pragma unroll
            for (int mt = 0; mt < 2; mt++)
#pragma unroll
                for (int r8 = 0; r8 < 2; r8++) {
                    float a = v1[mt][r8], bb = v2[mt][r8];
                    a += __shfl_xor_sync(0xFFFFFFFFu, a, 1);
                    a += __shfl_xor_sync(0xFFFFFFFFu, a, 2);
                    bb += __shfl_xor_sync(0xFFFFFFFFu, bb, 1);
                    bb += __shfl_xor_sync(0xFFFFFFFFu, bb, 2);
                    if (fq == 0) {
                        int k = k0 + mt * 16 + r8 * 8;
                        g_V1[k * NH + h] = a;
                        g_V2[k * NH + h] = bb;
                    }
                }
        }
    } else {                                             // ---- edgefeat (full row) ----
        int e = b - 256;
        int off = g_boff[e], cnt = g_bcnt[e];
        float bi = g_Binv[e];
        const float4* xl4 = (const float4*)g_xl;
        float4* ef4 = (float4*)g_ef;
#pragma unroll
        for (int y = 0; y < 4; y++) {
            int d4 = y * 256 + threadIdx.x;
            float4 acc = make_float4(0.f, 0.f, 0.f, 0.f);
            for (int t = 0; t < cnt; t++) {
                int i = g_csr[off + t];
                float4 v = xl4[(size_t)(i >> 3) * (HD / 4) + d4];
                acc.x += v.x; acc.y += v.y; acc.z += v.z; acc.w += v.w;
            }
            acc.x *= bi; acc.y *= bi; acc.z *= bi; acc.w *= bi;
            ef4[(size_t)e * (HD / 4) + d4] = acc;
        }
    }
}

// ---------------- k_gsx: blocks 0..143 tgG (split-K 2), 144..655 sxse2 ----------------
__global__ void __launch_bounds__(256) k_gsx(const float* __restrict__ feat) {
    extern __shared__ float dsm[];
    __shared__ float red[NH][256];
    int b = blockIdx.x;
    if (b < 144) {                                       // ---- tgG ----
        float acc[2][2][4] = {};
        float dv1[2][2], dv2[2][2];
        int kz = (b & 1) * 2048;
        int t = b >> 1;
        int m0 = (t & 3) * 128, n0 = (t >> 2) * 32;
        const float* A = g_featc + (size_t)m0 * HD + kz;
        const float* B = g_BcatT + (size_t)n0 * HD + kz;
        mma_v4<32, 64, false>(dsm, A, HD, B, HD, nullptr, acc, dv1, dv2);
        int lane = threadIdx.x & 31, wid = threadIdx.x >> 5;
        int rb = m0 + (wid >> 1) * 32 + (lane >> 2);
        int cb = n0 + (wid & 1) * 16 + 2 * (lane & 3);
#pragma unroll
        for (int mt = 0; mt < 2; mt++)
#pragma unroll
            for (int nt = 0; nt < 2; nt++) {
                int r = rb + mt * 16, cc = cb + nt * 8;
                atomicAdd(&g_G[(size_t)r * GC + cc],           acc[mt][nt][0]);
                atomicAdd(&g_G[(size_t)r * GC + cc + 1],       acc[mt][nt][1]);
                atomicAdd(&g_G[(size_t)(r + 8) * GC + cc],     acc[mt][nt][2]);
                atomicAdd(&g_G[(size_t)(r + 8) * GC + cc + 1], acc[mt][nt][3]);
            }
    } else {                                             // ---- sxse2: sx & s2n ----
        int n = b - 144;
        const float* row = feat + (size_t)n * HD;
        float a1[NH] = {}, a2[NH] = {};
        for (int k = threadIdx.x; k < HD; k += 256) {
            float xv = row[k];
            float4 w0 = *(const float4*)&g_V1[k * NH];
            float4 w1 = *(const float4*)&g_V1[k * NH + 4];
            a1[0] += xv * w0.x; a1[1] += xv * w0.y; a1[2] += xv * w0.z; a1[3] += xv * w0.w;
            a1[4] += xv * w1.x; a1[5] += xv * w1.y; a1[6] += xv * w1.z; a1[7] += xv * w1.w;
            float4 u0 = *(const float4*)&g_V2[k * NH];
            float4 u1 = *(const float4*)&g_V2[k * NH + 4];
            a2[0] += xv * u0.x; a2[1] += xv * u0.y; a2[2] += xv * u0.z; a2[3] += xv * u0.w;
            a2[4] += xv * u1.x; a2[5] += xv * u1.y; a2[6] += xv * u1.z; a2[7] += xv * u1.w;
        }
#pragma unroll
        for (int h = 0; h < NH; h++) red[h][threadIdx.x] = a1[h];
        __syncthreads();
        for (int s = 128; s > 0; s >>= 1) {
            if (threadIdx.x < s)
#pragma unroll
                for (int h = 0; h < NH; h++) red[h][threadIdx.x] += red[h][threadIdx.x + s];
            __syncthreads();
        }
        if (threadIdx.x < NH) g_sx[n * NH + threadIdx.x] = red[threadIdx.x][0];
        __syncthreads();
#pragma unroll
        for (int h = 0; h < NH; h++) red[h][threadIdx.x] = a2[h];
        __syncthreads();
        for (int s = 128; s > 0; s >>= 1) {
            if (threadIdx.x < s)
#pragma unroll
                for (int h = 0; h < NH; h++) red[h][threadIdx.x] += red[h][threadIdx.x + s];
            __syncthreads();
        }
        if (threadIdx.x < NH) g_s2n[n * NH + threadIdx.x] = red[threadIdx.x][0];
    }
}

// ---------------- se = per-edge mean of s2n ----------------
__global__ void k_se() {
    int id = blockIdx.x * 256 + threadIdx.x;             // EE*NH = 4096
    if (id >= EE * NH) return;
    int e = id >> 3, h = id & 7;
    int off = g_boff[e], cnt = g_bcnt[e];
    float s = 0.0f;
    for (int t = 0; t < cnt; t++) {
        int i = g_csr[off + t];
        s += g_s2n[(i >> 3) * NH + h];
    }
    g_se[e * NH + h] = s / (float)cnt;
}

// ---------------- fused prep: csr | xpad | W1T | W2T(+tail) | zero-G | bw2 ----------------
#define NB_CSR  64
#define NB_XPAD (NN*FTP/256)          // 2816
#define NB_W1T  ((FTP/32)*(HD/32))    // 5632
#define NB_W2T  ((HD/32)*(NC/32))     // 256
#define NB_GZ   (NN*GC/256)           // 1152
__global__ void __launch_bounds__(256) k_prepA(const int* __restrict__ edge,
                                               const float* __restrict__ x,
                                               const float* __restrict__ W1,
                                               const float* __restrict__ W2,
                                               const float* __restrict__ ba) {
    __shared__ int se_[NNZ];          // 16 KB (csr section)
    __shared__ float t[32][33];
    __shared__ float red[256];
    int b = blockIdx.x, tid = threadIdx.x;
    if (b < NB_CSR) {                                    // ---- CSR ----
        for (int i = tid; i < NNZ; i += 256) se_[i] = edge[i];
        __syncthreads();
        int lane = tid & 31;
        int e = b * 8 + (tid >> 5);
        int nlt = 0, cnt = 0;
        for (int i = lane; i < NNZ; i += 32) {
            int v = se_[i];
            nlt += __popc(__ballot_sync(0xFFFFFFFFu, v < e));
            cnt += __popc(__ballot_sync(0xFFFFFFFFu, v == e));
        }
        int w = nlt;
        for (int i = lane; i < NNZ; i += 32) {
            int v = se_[i];
            unsigned m = __ballot_sync(0xFFFFFFFFu, v == e);
            if (v == e)
                g_csr[w + __popc(m & ((1u << lane) - 1u))] = i;
            w += __popc(m);
        }
        if (lane == 0) {
            g_bcnt[e] = cnt;
            g_boff[e] = nlt;
            g_Binv[e] = (cnt > 0) ? 1.0f / (float)cnt : 0.0f;
        }
        return;
    }
    b -= NB_CSR;
    if (b < NB_XPAD) {                                   // ---- xpad ----
        int i = b * 256 + tid;
        int r = i / FTP, c = i % FTP;
        g_xpad[i] = (c < FT) ? tf32r(x[r * FT + c]) : 0.0f;
        return;
    }
    b -= NB_XPAD;
    if (b < NB_W1T) {                                    // ---- W1T transpose ----
        int ky = b / (HD / 32), nx = b % (HD / 32);
        int kb = ky * 32, nb = nx * 32;
        int tx = tid & 31, ty = tid >> 5;
        for (int i = ty; i < 32; i += 8) {
            int k = kb + i;
            t[i][tx] = (k < FT) ? tf32r(W1[(size_t)k * HD + nb + tx]) : 0.0f;
        }
        __syncthreads();
        for (int i = ty; i < 32; i += 8)
            g_W1T[(size_t)(nb + i) * FTP + kb + tx] = t[tx][i];
        return;
    }
    b -= NB_W1T;
    if (b < NB_W2T) {                                    // ---- W2T + BcatT tail ----
        int kb = (b >> 1) * 32, nb = (b & 1) * 32;
        int tx = tid & 31, ty = tid >> 5;
        for (int i = ty; i < 32; i += 8)
            t[i][tx] = tf32r(W2[(size_t)(kb + i) * NC + nb + tx]);
        __syncthreads();
        for (int i = ty; i < 32; i += 8) {
            float v = t[tx][i];
            g_W2T[(size_t)(nb + i) * HD + kb + tx] = v;
            g_BcatT[(size_t)(HC + nb + i) * HD + kb + tx] = v;
        }
        return;
    }
    b -= NB_W2T;
    if (b < NB_GZ) {                                     // ---- zero G ----
        g_G[b * 256 + tid] = 0.0f;
        return;
    }
    // ---- bw2 = ba @ W2 ----
    int c = tid & 63, sl = tid >> 6;
    float acc = 0.0f;
    for (int d = sl * 1024; d < (sl + 1) * 1024; d++) acc += ba[d] * W2[d * NC + c];
    red[tid] = acc;
    __syncthreads();
    if (sl == 0) g_bw2[c] = red[c] + red[c + 64] + red[c + 128] + red[c + 192];
}

// ---------------- k_feat ----------------
__global__ void __launch_bounds__(256) k_feat(const int* __restrict__ edge,
                                              const float* __restrict__ b1,
                                              float* __restrict__ feat) {
    int n = blockIdx.x;
    int d4 = blockIdx.y * 256 + threadIdx.x;
    float4 acc = make_float4(0.f, 0.f, 0.f, 0.f);
    const float4* ef4 = (const float4*)g_ef;
#pragma unroll
    for (int j = 0; j < KD; j++) {
        int e = edge[n * KD + j];
        float4 v = ef4[(size_t)e * (HD / 4) + d4];
        acc.x += v.x; acc.y += v.y; acc.z += v.z; acc.w += v.w;
    }
    float4 bb = ((const float4*)b1)[d4];
    float4 r, rc;
    r.x = fmaxf(acc.x * DINV + bb.x, 0.f);
    r.y = fmaxf(acc.y * DINV + bb.y, 0.f);
    r.z = fmaxf(acc.z * DINV + bb.z, 0.f);
    r.w = fmaxf(acc.w * DINV + bb.w, 0.f);
    rc.x = tf32r(r.x); rc.y = tf32r(r.y); rc.z = tf32r(r.z); rc.w = tf32r(r.w);
    ((float4*)feat)[(size_t)n * (HD / 4) + d4] = r;       // exact output #1
    ((float4*)g_featc)[(size_t)n * (HD / 4) + d4] = rc;   // rounded A for G gemm
}

// ---------------- softmax / aggregation ----------------
__global__ void k_alpha(const int* __restrict__ edge) {
    int id = blockIdx.x * blockDim.x + threadIdx.x;
    if (id >= NN * NH) return;
    int n = id >> 3, h = id & 7;
    float sxv = g_sx[n * NH + h];
    float l[KD];
    float m = -1e30f;
#pragma unroll
    for (int j = 0; j < KD; j++) {
        int e = edge[n * KD + j];
        float t = sxv + g_se[e * NH + h];
        t = t > 0.0f ? t : 0.2f * t;
        l[j] = t;
        m = fmaxf(m, t);
    }
    float s = 0.0f;
#pragma unroll
    for (int j = 0; j < KD; j++) { l[j] = expf(l[j] - m); s += l[j]; }
    float inv = 1.0f / s;
#pragma unroll
    for (int j = 0; j < KD; j++) g_alpha[(n * KD + j) * NH + h] = l[j] * inv;
}

__global__ void __launch_bounds__(256) k_R() {
    int e = blockIdx.x;
    int hc = blockIdx.y * 256 + threadIdx.x;
    int h = hc >> 6;
    int off = g_boff[e], cnt = g_bcnt[e];
    float acc = 0.0f;
    for (int t = 0; t < cnt; t++) {
        int i = g_csr[off + t];
        acc += g_alpha[i * NH + h] * g_G[(i >> 3) * GC + hc];
    }
    g_R[e * HC + hc] = acc * g_Binv[e];
}
__global__ void k_Y(const int* __restrict__ edge) {
    int n = blockIdx.x, c = threadIdx.x;
    float acc = g_G[n * GC + HC + c] + g_bw2[c];
    float s = 0.0f;
#pragma unroll
    for (int j = 0; j < KD; j++) {
        int e = edge[n * KD + j];
        const float* al = &g_alpha[(n * KD + j) * NH];
        const float* Rr = &g_R[e * HC + c];
#pragma unroll
        for (int h = 0; h < NH; h++) s += al[h] * Rr[h * NC];
    }
    g_Y[n * NC + c] = acc + s * DINV * (1.0f / NH);
}
__global__ void k_ef2() {
    int e = blockIdx.x, c = threadIdx.x;
    int off = g_boff[e], cnt = g_bcnt[e];
    float acc = 0.0f;
    for (int t = 0; t < cnt; t++) {
        int i = g_csr[off + t];
        acc += g_Y[(i >> 3) * NC + c];
    }
    g_ef2[e * NC + c] = acc * g_Binv[e];
}
__global__ void k_out(const int* __restrict__ edge, const float* __restrict__ b2,
                      float* __restrict__ out) {
    int n = blockIdx.x, c = threadIdx.x;
    float acc = 0.0f;
#pragma unroll
    for (int j = 0; j < KD; j++) {
        int e = edge[n * KD + j];
        acc += g_ef2[e * NC + c];
    }
    float hid = acc * DINV + b2[c];
    out[(size_t)NN * HD + n * NC + c] = hid;
    out[(size_t)NN * HD + NN * NC + n * NC + c] = tanhf(hid);
}

// ---------------- launch ----------------
extern "C" void kernel_launch(void* const* d_in, const int* in_sizes, int n_in,
                              void* d_out, int out_size) {
    const float* x    = (const float*)d_in[0];
    const int*   edge = (const int*)  d_in[2];
    const float* W1   = (const float*)d_in[3];
    const float* b1   = (const float*)d_in[4];
    const float* Wa   = (const float*)d_in[5];
    const float* att  = (const float*)d_in[6];
    const float* ba   = (const float*)d_in[7];
    const float* W2   = (const float*)d_in[8];
    const float* b2   = (const float*)d_in[9];
    float* out  = (float*)d_out;
    float* feat = out;

    cudaFuncSetAttribute(k_tg1,  cudaFuncAttributeMaxDynamicSharedMemorySize, SMEM_T1);
    cudaFuncSetAttribute(k_mvef, cudaFuncAttributeMaxDynamicSharedMemorySize, SMEM_MV);
    cudaFuncSetAttribute(k_gsx,  cudaFuncAttributeMaxDynamicSharedMemorySize, SMEM_GG);

    k_prepA<<<NB_CSR + NB_XPAD + NB_W1T + NB_W2T + NB_GZ + 1, 256>>>(edge, x, W1, W2, ba); // 1
    k_tg1<<<dim3(4, 64), 256, SMEM_T1>>>();                           // 2
    k_mvef<<<768, 256, SMEM_MV>>>(Wa, att);                           // 3  tgMV ∥ edgefeat
    k_feat<<<dim3(NN, 4), 256>>>(edge, b1, feat);                     // 4
    k_gsx<<<656, 256, SMEM_GG>>>(feat);                               // 5  tgG ∥ sxse2
    k_se<<<16, 256>>>();                                              // 6
    k_alpha<<<16, 256>>>(edge);                                       // 7
    k_R<<<dim3(EE, 2), 256>>>();                                      // 8
    k_Y<<<NN, 64>>>(edge);                                            // 9
    k_ef2<<<EE, 64>>>();                                              // 10
    k_out<<<NN, 64>>>(edge, b2, out);                                 // 11
}